// round 2
// baseline (speedup 1.0000x reference)
#include <cuda_runtime.h>
#include <cuda_bf16.h>

// ----------------------------------------------------------------------------
// Problem constants
// ----------------------------------------------------------------------------
#define BATCH   2
#define LQ      4096
#define LKV     1024
#define DIM     1024
#define KV_DIM  768
#define NHEADS  16
#define HDIM    64

// Scratch (device globals; allocation-free per harness rules)
__device__ float g_qtmp[(BATCH*LQ)*DIM];   // Q proj out; later reused as attention out
__device__ float g_q   [(BATCH*LQ)*DIM];   // Q after rmsnorm+rope
__device__ float g_ktmp[(BATCH*LKV)*DIM];  // K proj out
__device__ float g_k   [(BATCH*LKV)*DIM];  // K after rmsnorm+rope
__device__ float g_v   [(BATCH*LKV)*DIM];  // V proj out (used directly)

// ----------------------------------------------------------------------------
// SGEMM: C[M,N] = A[M,K] @ B[K,N] + bias[N]
// BM=BN=128, BK=16, 256 threads, 8x8 micro-tile. Requires M%128==0, N%128==0, K%16==0.
// ----------------------------------------------------------------------------
__global__ __launch_bounds__(256) void sgemm_bias_kernel(
    const float* __restrict__ A, const float* __restrict__ Bm,
    const float* __restrict__ bias, float* __restrict__ C,
    int M, int N, int K)
{
    __shared__ float As[16][132];   // [k][m] transposed, padded
    __shared__ float Bs[16][128];   // [k][n]

    const int tid = threadIdx.x;
    const int tr  = tid >> 4;       // 0..15
    const int tc  = tid & 15;       // 0..15
    const int bm  = blockIdx.y * 128;
    const int bn  = blockIdx.x * 128;

    float acc[8][8];
#pragma unroll
    for (int i = 0; i < 8; i++)
#pragma unroll
        for (int j = 0; j < 8; j++) acc[i][j] = 0.f;

    const int arow = tid >> 2;          // 0..63
    const int acol = (tid & 3) << 2;    // 0,4,8,12
    const int brow = tid >> 5;          // 0..7
    const int bcol = (tid & 31) << 2;   // 0..124

    for (int k0 = 0; k0 < K; k0 += 16) {
#pragma unroll
        for (int i = 0; i < 2; i++) {
            int r = arow + i * 64;
            float4 t = *(const float4*)&A[(long)(bm + r) * K + k0 + acol];
            As[acol    ][r] = t.x;
            As[acol + 1][r] = t.y;
            As[acol + 2][r] = t.z;
            As[acol + 3][r] = t.w;
        }
#pragma unroll
        for (int i = 0; i < 2; i++) {
            int r = brow + i * 8;
            *(float4*)&Bs[r][bcol] = *(const float4*)&Bm[(long)(k0 + r) * N + bn + bcol];
        }
        __syncthreads();

#pragma unroll
        for (int kk = 0; kk < 16; kk++) {
            float a[8], b[8];
            *(float4*)&a[0] = *(const float4*)&As[kk][tr * 8];
            *(float4*)&a[4] = *(const float4*)&As[kk][tr * 8 + 4];
            *(float4*)&b[0] = *(const float4*)&Bs[kk][tc * 8];
            *(float4*)&b[4] = *(const float4*)&Bs[kk][tc * 8 + 4];
#pragma unroll
            for (int i = 0; i < 8; i++)
#pragma unroll
                for (int j = 0; j < 8; j++)
                    acc[i][j] = fmaf(a[i], b[j], acc[i][j]);
        }
        __syncthreads();
    }

#pragma unroll
    for (int i = 0; i < 8; i++) {
        int r = bm + tr * 8 + i;
#pragma unroll
        for (int j = 0; j < 8; j += 4) {
            int c = bn + tc * 8 + j;
            float4 t;
            t.x = acc[i][j    ] + bias[c    ];
            t.y = acc[i][j + 1] + bias[c + 1];
            t.z = acc[i][j + 2] + bias[c + 2];
            t.w = acc[i][j + 3] + bias[c + 3];
            *(float4*)&C[(long)r * N + c] = t;
        }
    }
}

// ----------------------------------------------------------------------------
// Fused RMSNorm + RoPE. One block per row of 1024. cos/sin are (B,L,64)
// contiguous so index = row*64 + d.
// ----------------------------------------------------------------------------
__global__ __launch_bounds__(256) void normrope_kernel(
    const float* __restrict__ in, float* __restrict__ out,
    const float* __restrict__ g, const float* __restrict__ cosb,
    const float* __restrict__ sinb)
{
    const int row = blockIdx.x;
    const float* h = in + (long)row * DIM;
    const int tid = threadIdx.x;
    const int e = tid << 2;

    float4 t = *(const float4*)&h[e];
    float ss = t.x * t.x + t.y * t.y + t.z * t.z + t.w * t.w;
#pragma unroll
    for (int o = 16; o > 0; o >>= 1)
        ss += __shfl_xor_sync(0xffffffffu, ss, o);
    __shared__ float red[8];
    if ((tid & 31) == 0) red[tid >> 5] = ss;
    __syncthreads();
    float tot = red[0] + red[1] + red[2] + red[3] + red[4] + red[5] + red[6] + red[7];
    float inv = rsqrtf(tot * (1.0f / (float)DIM) + 1e-6f);

    const int d   = e & (HDIM - 1);
    const int po  = (d < 32) ? 32 : -32;
    const float sgn = (d < 32) ? -1.0f : 1.0f;

    float4 tp  = *(const float4*)&h[e + po];
    float4 g4  = *(const float4*)&g[e];
    float4 gp4 = *(const float4*)&g[e + po];
    float4 c4  = *(const float4*)&cosb[(long)row * HDIM + d];
    float4 s4  = *(const float4*)&sinb[(long)row * HDIM + d];

    float4 o4;
    o4.x = t.x * inv * g4.x * c4.x + sgn * tp.x * inv * gp4.x * s4.x;
    o4.y = t.y * inv * g4.y * c4.y + sgn * tp.y * inv * gp4.y * s4.y;
    o4.z = t.z * inv * g4.z * c4.z + sgn * tp.z * inv * gp4.z * s4.z;
    o4.w = t.w * inv * g4.w * c4.w + sgn * tp.w * inv * gp4.w * s4.w;
    *(float4*)&out[(long)row * DIM + e] = o4;
}

// ----------------------------------------------------------------------------
// Flash attention: one CTA per (b,h,q-tile of 64). KV chunks of 64, D=64.
// 256 threads as 16x16; each thread owns a 4x4 tile of S and of O.
//
// Shared = exactly 48KB static (no dynamic smem, no cudaFuncSetAttribute):
//   Qs: logical [d][r] 64x64, XOR-swizzled (transposed write 2-way, reads broadcast)
//   Ks: logical [d][c] 64x64, XOR-swizzled; REUSED as Ps [c][r] after S phase
//   Vs: logical [c][d] 64x64, natural layout (conflict-free both directions)
// Swizzle: inner ^ (((outer>>2)&7)<<2) — multiple of 4, so float4 stays aligned
// and contiguous.
// ----------------------------------------------------------------------------
__device__ __forceinline__ int swz64(int outer, int inner) {
    return (outer << 6) + (inner ^ (((outer >> 2) & 7) << 2));
}

__global__ __launch_bounds__(256) void attn_kernel(
    const float* __restrict__ q, const float* __restrict__ k,
    const float* __restrict__ v, float* __restrict__ o)
{
    __shared__ float Qs[64 * 64];
    __shared__ float Ks[64 * 64];   // K during S phase, P during PV phase
    __shared__ float Vs[64 * 64];

    const int tid = threadIdx.x;
    const int ty = tid >> 4, tx = tid & 15;
    const int b  = blockIdx.x >> 4;
    const int h  = blockIdx.x & 15;
    const int q0 = blockIdx.y << 6;
    const float scale = 0.125f;     // 1/sqrt(64)

    // Load Q tile (scaled), transposed to [d][r] with swizzle
    const float* qb = q + (long)(b * LQ + q0) * DIM + h * HDIM;
    {
        const int r  = tid >> 4;
        const int d4 = (tid & 15) << 2;
#pragma unroll
        for (int i = 0; i < 4; i++) {
            int rr = r + i * 16;
            float4 t = *(const float4*)&qb[rr * DIM + d4];
            Qs[swz64(d4    , rr)] = t.x * scale;
            Qs[swz64(d4 + 1, rr)] = t.y * scale;
            Qs[swz64(d4 + 2, rr)] = t.z * scale;
            Qs[swz64(d4 + 3, rr)] = t.w * scale;
        }
    }

    float m[4], l[4], acc[4][4];
#pragma unroll
    for (int i = 0; i < 4; i++) {
        m[i] = -1e30f; l[i] = 0.f;
#pragma unroll
        for (int j = 0; j < 4; j++) acc[i][j] = 0.f;
    }

    for (int j0 = 0; j0 < LKV; j0 += 64) {
        __syncthreads();  // prev PV done reading Ks(P)/Vs; first iter: Qs ready
        {
            const float* kb = k + (long)(b * LKV + j0) * DIM + h * HDIM;
            const float* vb = v + (long)(b * LKV + j0) * DIM + h * HDIM;
            const int c  = tid >> 4;
            const int d4 = (tid & 15) << 2;
#pragma unroll
            for (int i = 0; i < 4; i++) {
                int cc = c + i * 16;
                float4 t = *(const float4*)&kb[cc * DIM + d4];
                Ks[swz64(d4    , cc)] = t.x;
                Ks[swz64(d4 + 1, cc)] = t.y;
                Ks[swz64(d4 + 2, cc)] = t.z;
                Ks[swz64(d4 + 3, cc)] = t.w;
                *(float4*)&Vs[cc * 64 + d4] = *(const float4*)&vb[cc * DIM + d4];
            }
        }
        __syncthreads();

        // S = (scaled Q) K^T  — 4x4 per thread
        float s[4][4];
#pragma unroll
        for (int i = 0; i < 4; i++)
#pragma unroll
            for (int j = 0; j < 4; j++) s[i][j] = 0.f;
#pragma unroll 8
        for (int d = 0; d < 64; d++) {
            float4 a  = *(const float4*)&Qs[swz64(d, ty * 4)];
            float4 bb = *(const float4*)&Ks[swz64(d, tx * 4)];
            const float av[4] = {a.x, a.y, a.z, a.w};
            const float bv[4] = {bb.x, bb.y, bb.z, bb.w};
#pragma unroll
            for (int i = 0; i < 4; i++)
#pragma unroll
                for (int j = 0; j < 4; j++)
                    s[i][j] = fmaf(av[i], bv[j], s[i][j]);
        }

        // Online softmax: reduce across the 16 lanes sharing each row group
#pragma unroll
        for (int i = 0; i < 4; i++) {
            float mx = fmaxf(fmaxf(s[i][0], s[i][1]), fmaxf(s[i][2], s[i][3]));
#pragma unroll
            for (int ofs = 8; ofs > 0; ofs >>= 1)
                mx = fmaxf(mx, __shfl_xor_sync(0xffffffffu, mx, ofs, 16));
            float mn = fmaxf(m[i], mx);
            float f  = __expf(m[i] - mn);
            float rs = 0.f;
#pragma unroll
            for (int j = 0; j < 4; j++) {
                s[i][j] = __expf(s[i][j] - mn);
                rs += s[i][j];
            }
#pragma unroll
            for (int ofs = 8; ofs > 0; ofs >>= 1)
                rs += __shfl_xor_sync(0xffffffffu, rs, ofs, 16);
            m[i] = mn;
            l[i] = l[i] * f + rs;
#pragma unroll
            for (int j = 0; j < 4; j++) acc[i][j] *= f;
        }

        __syncthreads();  // everyone finished reading Ks — safe to overwrite with P

        // Stage P transposed ([c][r]) into the Ks buffer (swizzled)
#pragma unroll
        for (int j = 0; j < 4; j++) {
            float4 pv = make_float4(s[0][j], s[1][j], s[2][j], s[3][j]);
            *(float4*)&Ks[swz64(tx * 4 + j, ty * 4)] = pv;
        }
        __syncthreads();

        // O += P @ V
#pragma unroll 8
        for (int c = 0; c < 64; c++) {
            float4 a  = *(const float4*)&Ks[swz64(c, ty * 4)];
            float4 bb = *(const float4*)&Vs[c * 64 + tx * 4];
            const float av[4] = {a.x, a.y, a.z, a.w};
            const float bv[4] = {bb.x, bb.y, bb.z, bb.w};
#pragma unroll
            for (int i = 0; i < 4; i++)
#pragma unroll
                for (int j = 0; j < 4; j++)
                    acc[i][j] = fmaf(av[i], bv[j], acc[i][j]);
        }
    }

    // Normalize and write out
    float* ob = o + (long)(b * LQ + q0) * DIM + h * HDIM;
#pragma unroll
    for (int i = 0; i < 4; i++) {
        float inv = 1.0f / l[i];
        float4 t = make_float4(acc[i][0] * inv, acc[i][1] * inv,
                               acc[i][2] * inv, acc[i][3] * inv);
        *(float4*)&ob[(ty * 4 + i) * DIM + tx * 4] = t;
    }
}

// ----------------------------------------------------------------------------
// Launch
// ----------------------------------------------------------------------------
extern "C" void kernel_launch(void* const* d_in, const int* in_sizes, int n_in,
                              void* d_out, int out_size)
{
    const float* x     = (const float*)d_in[0];
    const float* y     = (const float*)d_in[1];
    const float* x_cos = (const float*)d_in[2];
    const float* x_sin = (const float*)d_in[3];
    const float* y_cos = (const float*)d_in[4];
    const float* y_sin = (const float*)d_in[5];
    const float* Wq    = (const float*)d_in[6];
    const float* bq    = (const float*)d_in[7];
    const float* Wk    = (const float*)d_in[8];
    const float* bk    = (const float*)d_in[9];
    const float* Wv    = (const float*)d_in[10];
    const float* bv    = (const float*)d_in[11];
    const float* Wo    = (const float*)d_in[12];
    const float* bo    = (const float*)d_in[13];
    const float* gq    = (const float*)d_in[14];
    const float* gk    = (const float*)d_in[15];
    float* out = (float*)d_out;

    float *qtmp, *qb, *ktmp, *kb, *vb;
    cudaGetSymbolAddress((void**)&qtmp, g_qtmp);
    cudaGetSymbolAddress((void**)&qb,   g_q);
    cudaGetSymbolAddress((void**)&ktmp, g_ktmp);
    cudaGetSymbolAddress((void**)&kb,   g_k);
    cudaGetSymbolAddress((void**)&vb,   g_v);

    const int Mq = BATCH * LQ;    // 8192
    const int Mk = BATCH * LKV;   // 2048

    // Projections
    sgemm_bias_kernel<<<dim3(DIM / 128, Mq / 128), 256>>>(x, Wq, bq, qtmp, Mq, DIM, DIM);
    sgemm_bias_kernel<<<dim3(DIM / 128, Mk / 128), 256>>>(y, Wk, bk, ktmp, Mk, DIM, KV_DIM);
    sgemm_bias_kernel<<<dim3(DIM / 128, Mk / 128), 256>>>(y, Wv, bv, vb,   Mk, DIM, KV_DIM);

    // RMSNorm + RoPE
    normrope_kernel<<<Mq, 256>>>(qtmp, qb, gq, x_cos, x_sin);
    normrope_kernel<<<Mk, 256>>>(ktmp, kb, gk, y_cos, y_sin);

    // Flash attention (writes into qtmp, which is free now)
    attn_kernel<<<dim3(BATCH * NHEADS, LQ / 64), 256>>>(qb, kb, vb, qtmp);

    // Output projection
    sgemm_bias_kernel<<<dim3(DIM / 128, Mq / 128), 256>>>(qtmp, Wo, bo, out, Mq, DIM, DIM);
}

// round 4
// speedup vs baseline: 1.3379x; 1.3379x over previous
#include <cuda_runtime.h>
#include <cuda_bf16.h>
#include <cstdint>

// ----------------------------------------------------------------------------
// Problem constants
// ----------------------------------------------------------------------------
#define BATCH   2
#define LQ      4096
#define LKV     1024
#define DIM     1024
#define KV_DIM  768
#define NHEADS  16
#define HDIM    64

// ----------------------------------------------------------------------------
// Scratch (device globals; allocation-free per harness rules)
// ----------------------------------------------------------------------------
__device__ float g_qtmp[(BATCH*LQ)*DIM];   // Q proj out; later attention out
__device__ float g_q   [(BATCH*LQ)*DIM];   // Q after rmsnorm+rope
__device__ float g_ktmp[(BATCH*LKV)*DIM];  // K proj out
__device__ float g_k   [(BATCH*LKV)*DIM];  // K after rmsnorm+rope
__device__ float g_v   [(BATCH*LKV)*DIM];  // V proj out

// bf16 split buffers
__device__ __nv_bfloat16 g_xhi[(BATCH*LQ)*DIM],  g_xlo[(BATCH*LQ)*DIM];   // x split; reused for attn-out split
__device__ __nv_bfloat16 g_yhi[(BATCH*LKV)*KV_DIM], g_ylo[(BATCH*LKV)*KV_DIM];
__device__ __nv_bfloat16 g_wqt_hi[DIM*DIM],    g_wqt_lo[DIM*DIM];     // Wq^T [N,K]
__device__ __nv_bfloat16 g_wkt_hi[DIM*KV_DIM], g_wkt_lo[DIM*KV_DIM];  // Wk^T
__device__ __nv_bfloat16 g_wvt_hi[DIM*KV_DIM], g_wvt_lo[DIM*KV_DIM];  // Wv^T
__device__ __nv_bfloat16 g_wot_hi[DIM*DIM],    g_wot_lo[DIM*DIM];     // Wo^T

// ----------------------------------------------------------------------------
// mma.sync m16n8k16 bf16 (baseline PTX, works on compute_103 virtual target)
// ----------------------------------------------------------------------------
#define MMA16816(d, a, b) \
    asm volatile("mma.sync.aligned.m16n8k16.row.col.f32.bf16.bf16.f32 " \
        "{%0,%1,%2,%3}, {%4,%5,%6,%7}, {%8,%9}, {%0,%1,%2,%3};" \
        : "+f"((d)[0]), "+f"((d)[1]), "+f"((d)[2]), "+f"((d)[3]) \
        : "r"((a)[0]), "r"((a)[1]), "r"((a)[2]), "r"((a)[3]), \
          "r"((b)[0]), "r"((b)[1]))

// ----------------------------------------------------------------------------
// bf16x3 GEMM: C[M,N] = A[M,K] @ Bt[N,K]^T + bias
//   A hi/lo bf16 [M,K] row-major; Bt hi/lo bf16 [N,K] row-major.
//   CTA tile 128x128, BK=32, 256 threads (8 warps, 2x4), warp tile 64x32.
//   Accumulates Ahi*Bhi + Ahi*Blo + Alo*Bhi in fp32.
//   SMEM stride 40 bf16 (80B rows) -> conflict-free 32-bit fragment loads.
// ----------------------------------------------------------------------------
#define SSTR 40

__global__ __launch_bounds__(256) void gemm_bf16x3_mma_kernel(
    const __nv_bfloat16* __restrict__ Ahi, const __nv_bfloat16* __restrict__ Alo,
    const __nv_bfloat16* __restrict__ Bhi, const __nv_bfloat16* __restrict__ Blo,
    const float* __restrict__ bias, float* __restrict__ C,
    int M, int N, int K)
{
    __shared__ __nv_bfloat16 sAhi[128 * SSTR];
    __shared__ __nv_bfloat16 sAlo[128 * SSTR];
    __shared__ __nv_bfloat16 sBhi[128 * SSTR];
    __shared__ __nv_bfloat16 sBlo[128 * SSTR];

    const int tid  = threadIdx.x;
    const int wid  = tid >> 5;
    const int lane = tid & 31;
    const int warpM = wid >> 2;          // 0..1  (64 rows each)
    const int warpN = wid & 3;           // 0..3  (32 cols each)
    const int bm = blockIdx.y * 128;
    const int bn = blockIdx.x * 128;

    const int tq = lane >> 2;            // 0..7
    const int tr = lane & 3;             // 0..3

    float acc[4][4][4];                  // [mf][nf][4]
#pragma unroll
    for (int i = 0; i < 4; i++)
#pragma unroll
        for (int j = 0; j < 4; j++)
#pragma unroll
            for (int r = 0; r < 4; r++) acc[i][j][r] = 0.f;

    // gmem->reg prefetch mapping: seg s in [0,512): r=s>>2, c16=s&3 (8 bf16 each)
    const int s0 = tid, s1 = tid + 256;
    const int r0g = s0 >> 2, c0g = (s0 & 3) * 8;
    const int r1g = s1 >> 2, c1g = (s1 & 3) * 8;

    float4 pAhi0, pAhi1, pAlo0, pAlo1, pBhi0, pBhi1, pBlo0, pBlo1;

    const int nchunks = K >> 5;   // BK=32

    {   // prefetch chunk 0
        const long a0 = (long)(bm + r0g) * K + c0g;
        const long a1 = (long)(bm + r1g) * K + c1g;
        const long b0 = (long)(bn + r0g) * K + c0g;
        const long b1 = (long)(bn + r1g) * K + c1g;
        pAhi0 = *(const float4*)&Ahi[a0]; pAhi1 = *(const float4*)&Ahi[a1];
        pAlo0 = *(const float4*)&Alo[a0]; pAlo1 = *(const float4*)&Alo[a1];
        pBhi0 = *(const float4*)&Bhi[b0]; pBhi1 = *(const float4*)&Bhi[b1];
        pBlo0 = *(const float4*)&Blo[b0]; pBlo1 = *(const float4*)&Blo[b1];
    }

    for (int c = 0; c < nchunks; c++) {
        // store prefetched chunk to smem
        *(float4*)&sAhi[r0g * SSTR + c0g] = pAhi0;
        *(float4*)&sAhi[r1g * SSTR + c1g] = pAhi1;
        *(float4*)&sAlo[r0g * SSTR + c0g] = pAlo0;
        *(float4*)&sAlo[r1g * SSTR + c1g] = pAlo1;
        *(float4*)&sBhi[r0g * SSTR + c0g] = pBhi0;
        *(float4*)&sBhi[r1g * SSTR + c1g] = pBhi1;
        *(float4*)&sBlo[r0g * SSTR + c0g] = pBlo0;
        *(float4*)&sBlo[r1g * SSTR + c1g] = pBlo1;
        __syncthreads();

        // prefetch next chunk
        if (c + 1 < nchunks) {
            const int k0 = (c + 1) << 5;
            const long a0 = (long)(bm + r0g) * K + k0 + c0g;
            const long a1 = (long)(bm + r1g) * K + k0 + c1g;
            const long b0 = (long)(bn + r0g) * K + k0 + c0g;
            const long b1 = (long)(bn + r1g) * K + k0 + c1g;
            pAhi0 = *(const float4*)&Ahi[a0]; pAhi1 = *(const float4*)&Ahi[a1];
            pAlo0 = *(const float4*)&Alo[a0]; pAlo1 = *(const float4*)&Alo[a1];
            pBhi0 = *(const float4*)&Bhi[b0]; pBhi1 = *(const float4*)&Bhi[b1];
            pBlo0 = *(const float4*)&Blo[b0]; pBlo1 = *(const float4*)&Blo[b1];
        }

        // compute: 2 k16-steps per chunk
#pragma unroll
        for (int ks = 0; ks < 2; ks++) {
            const int kb = ks * 16 + tr * 2;
            uint32_t ah[4][4], al[4][4], bh[4][2], bl[4][2];
#pragma unroll
            for (int mf = 0; mf < 4; mf++) {
                const int rA = warpM * 64 + mf * 16 + tq;
                ah[mf][0] = *(const uint32_t*)&sAhi[(rA    ) * SSTR + kb    ];
                ah[mf][1] = *(const uint32_t*)&sAhi[(rA + 8) * SSTR + kb    ];
                ah[mf][2] = *(const uint32_t*)&sAhi[(rA    ) * SSTR + kb + 8];
                ah[mf][3] = *(const uint32_t*)&sAhi[(rA + 8) * SSTR + kb + 8];
                al[mf][0] = *(const uint32_t*)&sAlo[(rA    ) * SSTR + kb    ];
                al[mf][1] = *(const uint32_t*)&sAlo[(rA + 8) * SSTR + kb    ];
                al[mf][2] = *(const uint32_t*)&sAlo[(rA    ) * SSTR + kb + 8];
                al[mf][3] = *(const uint32_t*)&sAlo[(rA + 8) * SSTR + kb + 8];
            }
#pragma unroll
            for (int nf = 0; nf < 4; nf++) {
                const int rB = warpN * 32 + nf * 8 + tq;
                bh[nf][0] = *(const uint32_t*)&sBhi[rB * SSTR + kb    ];
                bh[nf][1] = *(const uint32_t*)&sBhi[rB * SSTR + kb + 8];
                bl[nf][0] = *(const uint32_t*)&sBlo[rB * SSTR + kb    ];
                bl[nf][1] = *(const uint32_t*)&sBlo[rB * SSTR + kb + 8];
            }
#pragma unroll
            for (int mf = 0; mf < 4; mf++)
#pragma unroll
                for (int nf = 0; nf < 4; nf++) {
                    MMA16816(acc[mf][nf], ah[mf], bh[nf]);
                    MMA16816(acc[mf][nf], ah[mf], bl[nf]);
                    MMA16816(acc[mf][nf], al[mf], bh[nf]);
                }
        }
        __syncthreads();
    }

    // Epilogue: d0,d1 -> (row, col..col+1); d2,d3 -> (row+8, col..col+1)
#pragma unroll
    for (int mf = 0; mf < 4; mf++) {
        const int row = bm + warpM * 64 + mf * 16 + tq;
#pragma unroll
        for (int nf = 0; nf < 4; nf++) {
            const int col = bn + warpN * 32 + nf * 8 + tr * 2;
            const float b0 = bias[col], b1 = bias[col + 1];
            float2 v0 = make_float2(acc[mf][nf][0] + b0, acc[mf][nf][1] + b1);
            float2 v1 = make_float2(acc[mf][nf][2] + b0, acc[mf][nf][3] + b1);
            *(float2*)&C[(long)row * N + col]       = v0;
            *(float2*)&C[(long)(row + 8) * N + col] = v1;
        }
    }
}

// ----------------------------------------------------------------------------
// Split fp32 -> bf16 hi + lo (elementwise)
// ----------------------------------------------------------------------------
__global__ __launch_bounds__(256) void split_bf16_kernel(
    const float* __restrict__ src, __nv_bfloat16* __restrict__ hi,
    __nv_bfloat16* __restrict__ lo, int n4)
{
    int i = blockIdx.x * blockDim.x + threadIdx.x;
    if (i >= n4) return;
    float4 v = *(const float4*)&src[(long)i * 4];
    __nv_bfloat16 h0 = __float2bfloat16(v.x), h1 = __float2bfloat16(v.y);
    __nv_bfloat16 h2 = __float2bfloat16(v.z), h3 = __float2bfloat16(v.w);
    __nv_bfloat16 l0 = __float2bfloat16(v.x - __bfloat162float(h0));
    __nv_bfloat16 l1 = __float2bfloat16(v.y - __bfloat162float(h1));
    __nv_bfloat16 l2 = __float2bfloat16(v.z - __bfloat162float(h2));
    __nv_bfloat16 l3 = __float2bfloat16(v.w - __bfloat162float(h3));
    __nv_bfloat162 hp0, hp1, lp0, lp1;
    hp0.x = h0; hp0.y = h1; hp1.x = h2; hp1.y = h3;
    lp0.x = l0; lp0.y = l1; lp1.x = l2; lp1.y = l3;
    *(uint2*)&hi[(long)i * 4] = make_uint2(*(uint32_t*)&hp0, *(uint32_t*)&hp1);
    *(uint2*)&lo[(long)i * 4] = make_uint2(*(uint32_t*)&lp0, *(uint32_t*)&lp1);
}

// ----------------------------------------------------------------------------
// Split + transpose: W [K,N] fp32 -> Wt hi/lo [N,K] bf16
// ----------------------------------------------------------------------------
__global__ __launch_bounds__(256) void split_transpose_kernel(
    const float* __restrict__ W, __nv_bfloat16* __restrict__ Thi,
    __nv_bfloat16* __restrict__ Tlo, int K, int N)
{
    __shared__ float tile[32][33];
    const int bx = blockIdx.x * 32;   // N base
    const int by = blockIdx.y * 32;   // K base
    const int tx = threadIdx.x & 31;
    const int ty = threadIdx.x >> 5;  // 0..7
#pragma unroll
    for (int i = 0; i < 4; i++) {
        int kk = by + ty + i * 8;
        tile[ty + i * 8][tx] = W[(long)kk * N + bx + tx];
    }
    __syncthreads();
#pragma unroll
    for (int i = 0; i < 4; i++) {
        int nn = bx + ty + i * 8;
        float v = tile[tx][ty + i * 8];
        __nv_bfloat16 h = __float2bfloat16(v);
        __nv_bfloat16 l = __float2bfloat16(v - __bfloat162float(h));
        Thi[(long)nn * K + by + tx] = h;
        Tlo[(long)nn * K + by + tx] = l;
    }
}

// ----------------------------------------------------------------------------
// Fused RMSNorm + RoPE
// ----------------------------------------------------------------------------
__global__ __launch_bounds__(256) void normrope_kernel(
    const float* __restrict__ in, float* __restrict__ out,
    const float* __restrict__ g, const float* __restrict__ cosb,
    const float* __restrict__ sinb)
{
    const int row = blockIdx.x;
    const float* h = in + (long)row * DIM;
    const int tid = threadIdx.x;
    const int e = tid << 2;

    float4 t = *(const float4*)&h[e];
    float ss = t.x * t.x + t.y * t.y + t.z * t.z + t.w * t.w;
#pragma unroll
    for (int o = 16; o > 0; o >>= 1)
        ss += __shfl_xor_sync(0xffffffffu, ss, o);
    __shared__ float red[8];
    if ((tid & 31) == 0) red[tid >> 5] = ss;
    __syncthreads();
    float tot = red[0] + red[1] + red[2] + red[3] + red[4] + red[5] + red[6] + red[7];
    float inv = rsqrtf(tot * (1.0f / (float)DIM) + 1e-6f);

    const int d   = e & (HDIM - 1);
    const int po  = (d < 32) ? 32 : -32;
    const float sgn = (d < 32) ? -1.0f : 1.0f;

    float4 tp  = *(const float4*)&h[e + po];
    float4 g4  = *(const float4*)&g[e];
    float4 gp4 = *(const float4*)&g[e + po];
    float4 c4  = *(const float4*)&cosb[(long)row * HDIM + d];
    float4 s4  = *(const float4*)&sinb[(long)row * HDIM + d];

    float4 o4;
    o4.x = t.x * inv * g4.x * c4.x + sgn * tp.x * inv * gp4.x * s4.x;
    o4.y = t.y * inv * g4.y * c4.y + sgn * tp.y * inv * gp4.y * s4.y;
    o4.z = t.z * inv * g4.z * c4.z + sgn * tp.z * inv * gp4.z * s4.z;
    o4.w = t.w * inv * g4.w * c4.w + sgn * tp.w * inv * gp4.w * s4.w;
    *(float4*)&out[(long)row * DIM + e] = o4;
}

// ----------------------------------------------------------------------------
// Flash attention (fp32, unchanged from passing R2 kernel)
// ----------------------------------------------------------------------------
__device__ __forceinline__ int swz64(int outer, int inner) {
    return (outer << 6) + (inner ^ (((outer >> 2) & 7) << 2));
}

__global__ __launch_bounds__(256) void attn_kernel(
    const float* __restrict__ q, const float* __restrict__ k,
    const float* __restrict__ v, float* __restrict__ o)
{
    __shared__ float Qs[64 * 64];
    __shared__ float Ks[64 * 64];   // K during S phase, P during PV phase
    __shared__ float Vs[64 * 64];

    const int tid = threadIdx.x;
    const int ty = tid >> 4, tx = tid & 15;
    const int b  = blockIdx.x >> 4;
    const int h  = blockIdx.x & 15;
    const int q0 = blockIdx.y << 6;
    const float scale = 0.125f;

    const float* qb = q + (long)(b * LQ + q0) * DIM + h * HDIM;
    {
        const int r  = tid >> 4;
        const int d4 = (tid & 15) << 2;
#pragma unroll
        for (int i = 0; i < 4; i++) {
            int rr = r + i * 16;
            float4 t = *(const float4*)&qb[rr * DIM + d4];
            Qs[swz64(d4    , rr)] = t.x * scale;
            Qs[swz64(d4 + 1, rr)] = t.y * scale;
            Qs[swz64(d4 + 2, rr)] = t.z * scale;
            Qs[swz64(d4 + 3, rr)] = t.w * scale;
        }
    }

    float m[4], l[4], acc[4][4];
#pragma unroll
    for (int i = 0; i < 4; i++) {
        m[i] = -1e30f; l[i] = 0.f;
#pragma unroll
        for (int j = 0; j < 4; j++) acc[i][j] = 0.f;
    }

    for (int j0 = 0; j0 < LKV; j0 += 64) {
        __syncthreads();
        {
            const float* kb = k + (long)(b * LKV + j0) * DIM + h * HDIM;
            const float* vb = v + (long)(b * LKV + j0) * DIM + h * HDIM;
            const int c  = tid >> 4;
            const int d4 = (tid & 15) << 2;
#pragma unroll
            for (int i = 0; i < 4; i++) {
                int cc = c + i * 16;
                float4 t = *(const float4*)&kb[cc * DIM + d4];
                Ks[swz64(d4    , cc)] = t.x;
                Ks[swz64(d4 + 1, cc)] = t.y;
                Ks[swz64(d4 + 2, cc)] = t.z;
                Ks[swz64(d4 + 3, cc)] = t.w;
                *(float4*)&Vs[cc * 64 + d4] = *(const float4*)&vb[cc * DIM + d4];
            }
        }
        __syncthreads();

        float s[4][4];
#pragma unroll
        for (int i = 0; i < 4; i++)
#pragma unroll
            for (int j = 0; j < 4; j++) s[i][j] = 0.f;
#pragma unroll 8
        for (int d = 0; d < 64; d++) {
            float4 a  = *(const float4*)&Qs[swz64(d, ty * 4)];
            float4 bb = *(const float4*)&Ks[swz64(d, tx * 4)];
            const float av[4] = {a.x, a.y, a.z, a.w};
            const float bv[4] = {bb.x, bb.y, bb.z, bb.w};
#pragma unroll
            for (int i = 0; i < 4; i++)
#pragma unroll
                for (int j = 0; j < 4; j++)
                    s[i][j] = fmaf(av[i], bv[j], s[i][j]);
        }

#pragma unroll
        for (int i = 0; i < 4; i++) {
            float mx = fmaxf(fmaxf(s[i][0], s[i][1]), fmaxf(s[i][2], s[i][3]));
#pragma unroll
            for (int ofs = 8; ofs > 0; ofs >>= 1)
                mx = fmaxf(mx, __shfl_xor_sync(0xffffffffu, mx, ofs, 16));
            float mn = fmaxf(m[i], mx);
            float f  = __expf(m[i] - mn);
            float rs = 0.f;
#pragma unroll
            for (int j = 0; j < 4; j++) {
                s[i][j] = __expf(s[i][j] - mn);
                rs += s[i][j];
            }
#pragma unroll
            for (int ofs = 8; ofs > 0; ofs >>= 1)
                rs += __shfl_xor_sync(0xffffffffu, rs, ofs, 16);
            m[i] = mn;
            l[i] = l[i] * f + rs;
#pragma unroll
            for (int j = 0; j < 4; j++) acc[i][j] *= f;
        }

        __syncthreads();

#pragma unroll
        for (int j = 0; j < 4; j++) {
            float4 pv = make_float4(s[0][j], s[1][j], s[2][j], s[3][j]);
            *(float4*)&Ks[swz64(tx * 4 + j, ty * 4)] = pv;
        }
        __syncthreads();

#pragma unroll 8
        for (int c = 0; c < 64; c++) {
            float4 a  = *(const float4*)&Ks[swz64(c, ty * 4)];
            float4 bb = *(const float4*)&Vs[c * 64 + tx * 4];
            const float av[4] = {a.x, a.y, a.z, a.w};
            const float bv[4] = {bb.x, bb.y, bb.z, bb.w};
#pragma unroll
            for (int i = 0; i < 4; i++)
#pragma unroll
                for (int j = 0; j < 4; j++)
                    acc[i][j] = fmaf(av[i], bv[j], acc[i][j]);
        }
    }

    float* ob = o + (long)(b * LQ + q0) * DIM + h * HDIM;
#pragma unroll
    for (int i = 0; i < 4; i++) {
        float inv = 1.0f / l[i];
        float4 t = make_float4(acc[i][0] * inv, acc[i][1] * inv,
                               acc[i][2] * inv, acc[i][3] * inv);
        *(float4*)&ob[(ty * 4 + i) * DIM + tx * 4] = t;
    }
}

// ----------------------------------------------------------------------------
// Launch
// ----------------------------------------------------------------------------
extern "C" void kernel_launch(void* const* d_in, const int* in_sizes, int n_in,
                              void* d_out, int out_size)
{
    const float* x     = (const float*)d_in[0];
    const float* y     = (const float*)d_in[1];
    const float* x_cos = (const float*)d_in[2];
    const float* x_sin = (const float*)d_in[3];
    const float* y_cos = (const float*)d_in[4];
    const float* y_sin = (const float*)d_in[5];
    const float* Wq    = (const float*)d_in[6];
    const float* bq    = (const float*)d_in[7];
    const float* Wk    = (const float*)d_in[8];
    const float* bk    = (const float*)d_in[9];
    const float* Wv    = (const float*)d_in[10];
    const float* bv    = (const float*)d_in[11];
    const float* Wo    = (const float*)d_in[12];
    const float* bo    = (const float*)d_in[13];
    const float* gq    = (const float*)d_in[14];
    const float* gk    = (const float*)d_in[15];
    float* out = (float*)d_out;

    float *qtmp, *qb, *ktmp, *kb, *vb;
    cudaGetSymbolAddress((void**)&qtmp, g_qtmp);
    cudaGetSymbolAddress((void**)&qb,   g_q);
    cudaGetSymbolAddress((void**)&ktmp, g_ktmp);
    cudaGetSymbolAddress((void**)&kb,   g_k);
    cudaGetSymbolAddress((void**)&vb,   g_v);

    __nv_bfloat16 *xhi, *xlo, *yhi, *ylo;
    __nv_bfloat16 *wqh, *wql, *wkh, *wkl, *wvh, *wvl, *woh, *wol;
    cudaGetSymbolAddress((void**)&xhi, g_xhi);
    cudaGetSymbolAddress((void**)&xlo, g_xlo);
    cudaGetSymbolAddress((void**)&yhi, g_yhi);
    cudaGetSymbolAddress((void**)&ylo, g_ylo);
    cudaGetSymbolAddress((void**)&wqh, g_wqt_hi);
    cudaGetSymbolAddress((void**)&wql, g_wqt_lo);
    cudaGetSymbolAddress((void**)&wkh, g_wkt_hi);
    cudaGetSymbolAddress((void**)&wkl, g_wkt_lo);
    cudaGetSymbolAddress((void**)&wvh, g_wvt_hi);
    cudaGetSymbolAddress((void**)&wvl, g_wvt_lo);
    cudaGetSymbolAddress((void**)&woh, g_wot_hi);
    cudaGetSymbolAddress((void**)&wol, g_wot_lo);

    const int Mq = BATCH * LQ;    // 8192
    const int Mk = BATCH * LKV;   // 2048

    // Split activations + weights
    split_bf16_kernel<<<(Mq * DIM / 4 + 255) / 256, 256>>>(x, xhi, xlo, Mq * DIM / 4);
    split_bf16_kernel<<<(Mk * KV_DIM / 4 + 255) / 256, 256>>>(y, yhi, ylo, Mk * KV_DIM / 4);
    split_transpose_kernel<<<dim3(DIM / 32, DIM / 32),    256>>>(Wq, wqh, wql, DIM,    DIM);
    split_transpose_kernel<<<dim3(DIM / 32, KV_DIM / 32), 256>>>(Wk, wkh, wkl, KV_DIM, DIM);
    split_transpose_kernel<<<dim3(DIM / 32, KV_DIM / 32), 256>>>(Wv, wvh, wvl, KV_DIM, DIM);
    split_transpose_kernel<<<dim3(DIM / 32, DIM / 32),    256>>>(Wo, woh, wol, DIM,    DIM);

    // Projections (mma.sync bf16x3)
    gemm_bf16x3_mma_kernel<<<dim3(DIM / 128, Mq / 128), 256>>>(
        xhi, xlo, wqh, wql, bq, qtmp, Mq, DIM, DIM);
    gemm_bf16x3_mma_kernel<<<dim3(DIM / 128, Mk / 128), 256>>>(
        yhi, ylo, wkh, wkl, bk, ktmp, Mk, DIM, KV_DIM);
    gemm_bf16x3_mma_kernel<<<dim3(DIM / 128, Mk / 128), 256>>>(
        yhi, ylo, wvh, wvl, bv, vb, Mk, DIM, KV_DIM);

    // RMSNorm + RoPE
    normrope_kernel<<<Mq, 256>>>(qtmp, qb, gq, x_cos, x_sin);
    normrope_kernel<<<Mk, 256>>>(ktmp, kb, gk, y_cos, y_sin);

    // Flash attention (fp32) -> qtmp
    attn_kernel<<<dim3(BATCH * NHEADS, LQ / 64), 256>>>(qb, kb, vb, qtmp);

    // Split attention output (reuse x split buffers), then O projection
    split_bf16_kernel<<<(Mq * DIM / 4 + 255) / 256, 256>>>(qtmp, xhi, xlo, Mq * DIM / 4);
    gemm_bf16x3_mma_kernel<<<dim3(DIM / 128, Mq / 128), 256>>>(
        xhi, xlo, woh, wol, bo, out, Mq, DIM, DIM);
}

// round 6
// speedup vs baseline: 2.2734x; 1.6992x over previous
#include <cuda_runtime.h>
#include <cuda_bf16.h>
#include <cstdint>

// ----------------------------------------------------------------------------
// Problem constants
// ----------------------------------------------------------------------------
#define BATCH   2
#define LQ      4096
#define LKV     1024
#define DIM     1024
#define KV_DIM  768
#define NHEADS  16
#define HDIM    64

// ----------------------------------------------------------------------------
// Scratch (device globals; allocation-free per harness rules)
// ----------------------------------------------------------------------------
__device__ float g_qtmp[(BATCH*LQ)*DIM];   // Q proj out (fp32)
__device__ float g_ktmp[(BATCH*LKV)*DIM];  // K proj out (fp32)
__device__ float g_v   [(BATCH*LKV)*DIM];  // V proj out (fp32)

__device__ __nv_bfloat16 g_qhi[(BATCH*LQ)*DIM],  g_qlo[(BATCH*LQ)*DIM];   // Q normrope bf16
__device__ __nv_bfloat16 g_khi[(BATCH*LKV)*DIM], g_klo[(BATCH*LKV)*DIM];  // K normrope bf16
__device__ __nv_bfloat16 g_vthi[(BATCH*LKV)*DIM], g_vtlo[(BATCH*LKV)*DIM]; // V^T [b,h,d,c]

__device__ __nv_bfloat16 g_xhi[(BATCH*LQ)*DIM],  g_xlo[(BATCH*LQ)*DIM];   // x split; later attn-out split
__device__ __nv_bfloat16 g_yhi[(BATCH*LKV)*KV_DIM], g_ylo[(BATCH*LKV)*KV_DIM];
__device__ __nv_bfloat16 g_wqt_hi[DIM*DIM],    g_wqt_lo[DIM*DIM];
__device__ __nv_bfloat16 g_wkt_hi[DIM*KV_DIM], g_wkt_lo[DIM*KV_DIM];
__device__ __nv_bfloat16 g_wvt_hi[DIM*KV_DIM], g_wvt_lo[DIM*KV_DIM];
__device__ __nv_bfloat16 g_wot_hi[DIM*DIM],    g_wot_lo[DIM*DIM];

// ----------------------------------------------------------------------------
// mma.sync m16n8k16 bf16 helpers
// ----------------------------------------------------------------------------
#define MMA16816(d, a, b) \
    asm volatile("mma.sync.aligned.m16n8k16.row.col.f32.bf16.bf16.f32 " \
        "{%0,%1,%2,%3}, {%4,%5,%6,%7}, {%8,%9}, {%0,%1,%2,%3};" \
        : "+f"((d)[0]), "+f"((d)[1]), "+f"((d)[2]), "+f"((d)[3]) \
        : "r"((a)[0]), "r"((a)[1]), "r"((a)[2]), "r"((a)[3]), \
          "r"((b)[0]), "r"((b)[1]))

__device__ __forceinline__ uint32_t packbf2(float x, float y) {
    __nv_bfloat162 t = __float22bfloat162_rn(make_float2(x, y));
    return *reinterpret_cast<uint32_t*>(&t);
}

// ----------------------------------------------------------------------------
// bf16x3 GEMM: C[M,N] = A[M,K] @ Bt[N,K]^T + bias   (unchanged from R4)
// ----------------------------------------------------------------------------
#define SSTR 40

__global__ __launch_bounds__(256) void gemm_bf16x3_mma_kernel(
    const __nv_bfloat16* __restrict__ Ahi, const __nv_bfloat16* __restrict__ Alo,
    const __nv_bfloat16* __restrict__ Bhi, const __nv_bfloat16* __restrict__ Blo,
    const float* __restrict__ bias, float* __restrict__ C,
    int M, int N, int K)
{
    __shared__ __nv_bfloat16 sAhi[128 * SSTR];
    __shared__ __nv_bfloat16 sAlo[128 * SSTR];
    __shared__ __nv_bfloat16 sBhi[128 * SSTR];
    __shared__ __nv_bfloat16 sBlo[128 * SSTR];

    const int tid  = threadIdx.x;
    const int wid  = tid >> 5;
    const int lane = tid & 31;
    const int warpM = wid >> 2;
    const int warpN = wid & 3;
    const int bm = blockIdx.y * 128;
    const int bn = blockIdx.x * 128;

    const int tq = lane >> 2;
    const int tr = lane & 3;

    float acc[4][4][4];
#pragma unroll
    for (int i = 0; i < 4; i++)
#pragma unroll
        for (int j = 0; j < 4; j++)
#pragma unroll
            for (int r = 0; r < 4; r++) acc[i][j][r] = 0.f;

    const int s0 = tid, s1 = tid + 256;
    const int r0g = s0 >> 2, c0g = (s0 & 3) * 8;
    const int r1g = s1 >> 2, c1g = (s1 & 3) * 8;

    float4 pAhi0, pAhi1, pAlo0, pAlo1, pBhi0, pBhi1, pBlo0, pBlo1;

    const int nchunks = K >> 5;

    {
        const long a0 = (long)(bm + r0g) * K + c0g;
        const long a1 = (long)(bm + r1g) * K + c1g;
        const long b0 = (long)(bn + r0g) * K + c0g;
        const long b1 = (long)(bn + r1g) * K + c1g;
        pAhi0 = *(const float4*)&Ahi[a0]; pAhi1 = *(const float4*)&Ahi[a1];
        pAlo0 = *(const float4*)&Alo[a0]; pAlo1 = *(const float4*)&Alo[a1];
        pBhi0 = *(const float4*)&Bhi[b0]; pBhi1 = *(const float4*)&Bhi[b1];
        pBlo0 = *(const float4*)&Blo[b0]; pBlo1 = *(const float4*)&Blo[b1];
    }

    for (int c = 0; c < nchunks; c++) {
        *(float4*)&sAhi[r0g * SSTR + c0g] = pAhi0;
        *(float4*)&sAhi[r1g * SSTR + c1g] = pAhi1;
        *(float4*)&sAlo[r0g * SSTR + c0g] = pAlo0;
        *(float4*)&sAlo[r1g * SSTR + c1g] = pAlo1;
        *(float4*)&sBhi[r0g * SSTR + c0g] = pBhi0;
        *(float4*)&sBhi[r1g * SSTR + c1g] = pBhi1;
        *(float4*)&sBlo[r0g * SSTR + c0g] = pBlo0;
        *(float4*)&sBlo[r1g * SSTR + c1g] = pBlo1;
        __syncthreads();

        if (c + 1 < nchunks) {
            const int k0 = (c + 1) << 5;
            const long a0 = (long)(bm + r0g) * K + k0 + c0g;
            const long a1 = (long)(bm + r1g) * K + k0 + c1g;
            const long b0 = (long)(bn + r0g) * K + k0 + c0g;
            const long b1 = (long)(bn + r1g) * K + k0 + c1g;
            pAhi0 = *(const float4*)&Ahi[a0]; pAhi1 = *(const float4*)&Ahi[a1];
            pAlo0 = *(const float4*)&Alo[a0]; pAlo1 = *(const float4*)&Alo[a1];
            pBhi0 = *(const float4*)&Bhi[b0]; pBhi1 = *(const float4*)&Bhi[b1];
            pBlo0 = *(const float4*)&Blo[b0]; pBlo1 = *(const float4*)&Blo[b1];
        }

#pragma unroll
        for (int ks = 0; ks < 2; ks++) {
            const int kb = ks * 16 + tr * 2;
            uint32_t ah[4][4], al[4][4], bh[4][2], bl[4][2];
#pragma unroll
            for (int mf = 0; mf < 4; mf++) {
                const int rA = warpM * 64 + mf * 16 + tq;
                ah[mf][0] = *(const uint32_t*)&sAhi[(rA    ) * SSTR + kb    ];
                ah[mf][1] = *(const uint32_t*)&sAhi[(rA + 8) * SSTR + kb    ];
                ah[mf][2] = *(const uint32_t*)&sAhi[(rA    ) * SSTR + kb + 8];
                ah[mf][3] = *(const uint32_t*)&sAhi[(rA + 8) * SSTR + kb + 8];
                al[mf][0] = *(const uint32_t*)&sAlo[(rA    ) * SSTR + kb    ];
                al[mf][1] = *(const uint32_t*)&sAlo[(rA + 8) * SSTR + kb    ];
                al[mf][2] = *(const uint32_t*)&sAlo[(rA    ) * SSTR + kb + 8];
                al[mf][3] = *(const uint32_t*)&sAlo[(rA + 8) * SSTR + kb + 8];
            }
#pragma unroll
            for (int nf = 0; nf < 4; nf++) {
                const int rB = warpN * 32 + nf * 8 + tq;
                bh[nf][0] = *(const uint32_t*)&sBhi[rB * SSTR + kb    ];
                bh[nf][1] = *(const uint32_t*)&sBhi[rB * SSTR + kb + 8];
                bl[nf][0] = *(const uint32_t*)&sBlo[rB * SSTR + kb    ];
                bl[nf][1] = *(const uint32_t*)&sBlo[rB * SSTR + kb + 8];
            }
#pragma unroll
            for (int mf = 0; mf < 4; mf++)
#pragma unroll
                for (int nf = 0; nf < 4; nf++) {
                    MMA16816(acc[mf][nf], ah[mf], bh[nf]);
                    MMA16816(acc[mf][nf], ah[mf], bl[nf]);
                    MMA16816(acc[mf][nf], al[mf], bh[nf]);
                }
        }
        __syncthreads();
    }

#pragma unroll
    for (int mf = 0; mf < 4; mf++) {
        const int row = bm + warpM * 64 + mf * 16 + tq;
#pragma unroll
        for (int nf = 0; nf < 4; nf++) {
            const int col = bn + warpN * 32 + nf * 8 + tr * 2;
            const float b0 = bias[col], b1 = bias[col + 1];
            float2 v0 = make_float2(acc[mf][nf][0] + b0, acc[mf][nf][1] + b1);
            float2 v1 = make_float2(acc[mf][nf][2] + b0, acc[mf][nf][3] + b1);
            *(float2*)&C[(long)row * N + col]       = v0;
            *(float2*)&C[(long)(row + 8) * N + col] = v1;
        }
    }
}

// ----------------------------------------------------------------------------
// Split fp32 -> bf16 hi + lo (elementwise)
// ----------------------------------------------------------------------------
__global__ __launch_bounds__(256) void split_bf16_kernel(
    const float* __restrict__ src, __nv_bfloat16* __restrict__ hi,
    __nv_bfloat16* __restrict__ lo, int n4)
{
    int i = blockIdx.x * blockDim.x + threadIdx.x;
    if (i >= n4) return;
    float4 v = *(const float4*)&src[(long)i * 4];
    __nv_bfloat16 h0 = __float2bfloat16(v.x), h1 = __float2bfloat16(v.y);
    __nv_bfloat16 h2 = __float2bfloat16(v.z), h3 = __float2bfloat16(v.w);
    uint32_t ph0 = packbf2(v.x, v.y), ph1 = packbf2(v.z, v.w);
    uint32_t pl0 = packbf2(v.x - __bfloat162float(h0), v.y - __bfloat162float(h1));
    uint32_t pl1 = packbf2(v.z - __bfloat162float(h2), v.w - __bfloat162float(h3));
    *(uint2*)&hi[(long)i * 4] = make_uint2(ph0, ph1);
    *(uint2*)&lo[(long)i * 4] = make_uint2(pl0, pl1);
}

// ----------------------------------------------------------------------------
// Split + transpose: W [K,N] fp32 -> Wt hi/lo [N,K] bf16
// ----------------------------------------------------------------------------
__global__ __launch_bounds__(256) void split_transpose_kernel(
    const float* __restrict__ W, __nv_bfloat16* __restrict__ Thi,
    __nv_bfloat16* __restrict__ Tlo, int K, int N)
{
    __shared__ float tile[32][33];
    const int bx = blockIdx.x * 32;
    const int by = blockIdx.y * 32;
    const int tx = threadIdx.x & 31;
    const int ty = threadIdx.x >> 5;
#pragma unroll
    for (int i = 0; i < 4; i++) {
        int kk = by + ty + i * 8;
        tile[ty + i * 8][tx] = W[(long)kk * N + bx + tx];
    }
    __syncthreads();
#pragma unroll
    for (int i = 0; i < 4; i++) {
        int nn = bx + ty + i * 8;
        float v = tile[tx][ty + i * 8];
        __nv_bfloat16 h = __float2bfloat16(v);
        __nv_bfloat16 l = __float2bfloat16(v - __bfloat162float(h));
        Thi[(long)nn * K + by + tx] = h;
        Tlo[(long)nn * K + by + tx] = l;
    }
}

// ----------------------------------------------------------------------------
// V transpose-split: V [B*Lkv, DIM] fp32 -> Vt hi/lo [b,h,d][Lkv] bf16
// ----------------------------------------------------------------------------
__global__ __launch_bounds__(256) void vtrans_split_kernel(
    const float* __restrict__ V, __nv_bfloat16* __restrict__ Thi,
    __nv_bfloat16* __restrict__ Tlo)
{
    __shared__ float tile[32][33];
    const int bx = blockIdx.x * 32;   // col base (h*64+d)
    const int by = blockIdx.y * 32;   // row base (b*1024+c)
    const int tx = threadIdx.x & 31;
    const int ty = threadIdx.x >> 5;
#pragma unroll
    for (int i = 0; i < 4; i++) {
        int rr = by + ty + i * 8;
        tile[ty + i * 8][tx] = V[(long)rr * DIM + bx + tx];
    }
    __syncthreads();
#pragma unroll
    for (int i = 0; i < 4; i++) {
        int colg = bx + ty + i * 8;       // h*64+d
        int rowg = by + tx;               // b*1024+c
        int b = rowg >> 10, c = rowg & 1023;
        int h = colg >> 6,  d = colg & 63;
        float v = tile[tx][ty + i * 8];
        __nv_bfloat16 hh = __float2bfloat16(v);
        __nv_bfloat16 ll = __float2bfloat16(v - __bfloat162float(hh));
        long o = ((long)((b * NHEADS + h) * HDIM + d)) * LKV + c;
        Thi[o] = hh;
        Tlo[o] = ll;
    }
}

// ----------------------------------------------------------------------------
// Fused RMSNorm + RoPE -> bf16 hi/lo outputs
// ----------------------------------------------------------------------------
__global__ __launch_bounds__(256) void normrope_bf16_kernel(
    const float* __restrict__ in, __nv_bfloat16* __restrict__ outhi,
    __nv_bfloat16* __restrict__ outlo,
    const float* __restrict__ g, const float* __restrict__ cosb,
    const float* __restrict__ sinb)
{
    const int row = blockIdx.x;
    const float* h = in + (long)row * DIM;
    const int tid = threadIdx.x;
    const int e = tid << 2;

    float4 t = *(const float4*)&h[e];
    float ss = t.x * t.x + t.y * t.y + t.z * t.z + t.w * t.w;
#pragma unroll
    for (int o = 16; o > 0; o >>= 1)
        ss += __shfl_xor_sync(0xffffffffu, ss, o);
    __shared__ float red[8];
    if ((tid & 31) == 0) red[tid >> 5] = ss;
    __syncthreads();
    float tot = red[0] + red[1] + red[2] + red[3] + red[4] + red[5] + red[6] + red[7];
    float inv = rsqrtf(tot * (1.0f / (float)DIM) + 1e-6f);

    const int d   = e & (HDIM - 1);
    const int po  = (d < 32) ? 32 : -32;
    const float sgn = (d < 32) ? -1.0f : 1.0f;

    float4 tp  = *(const float4*)&h[e + po];
    float4 g4  = *(const float4*)&g[e];
    float4 gp4 = *(const float4*)&g[e + po];
    float4 c4  = *(const float4*)&cosb[(long)row * HDIM + d];
    float4 s4  = *(const float4*)&sinb[(long)row * HDIM + d];

    float4 o4;
    o4.x = t.x * inv * g4.x * c4.x + sgn * tp.x * inv * gp4.x * s4.x;
    o4.y = t.y * inv * g4.y * c4.y + sgn * tp.y * inv * gp4.y * s4.y;
    o4.z = t.z * inv * g4.z * c4.z + sgn * tp.z * inv * gp4.z * s4.z;
    o4.w = t.w * inv * g4.w * c4.w + sgn * tp.w * inv * gp4.w * s4.w;

    __nv_bfloat16 h0 = __float2bfloat16(o4.x), h1 = __float2bfloat16(o4.y);
    __nv_bfloat16 h2 = __float2bfloat16(o4.z), h3 = __float2bfloat16(o4.w);
    uint32_t ph0 = packbf2(o4.x, o4.y), ph1 = packbf2(o4.z, o4.w);
    uint32_t pl0 = packbf2(o4.x - __bfloat162float(h0), o4.y - __bfloat162float(h1));
    uint32_t pl1 = packbf2(o4.z - __bfloat162float(h2), o4.w - __bfloat162float(h3));
    *(uint2*)&outhi[(long)row * DIM + e] = make_uint2(ph0, ph1);
    *(uint2*)&outlo[(long)row * DIM + e] = make_uint2(pl0, pl1);
}

// ----------------------------------------------------------------------------
// Flash attention, bf16x3 mma.sync.
// CTA = 128 threads (4 warps), 64 q-rows per CTA (16 per warp).
// KV chunks of 64; K natural [c][d] bf16, V transposed [d][c] bf16 in smem.
// P kept in registers (D-frag layout == A-frag layout).
// ----------------------------------------------------------------------------
#define SK 72   // smem stride (bf16 elems): (tq*144 + tr*4)/4 % 32 = 4tq+tr, conflict-free

__global__ __launch_bounds__(128) void attn_mma_kernel(
    const __nv_bfloat16* __restrict__ qhi, const __nv_bfloat16* __restrict__ qlo,
    const __nv_bfloat16* __restrict__ khi, const __nv_bfloat16* __restrict__ klo,
    const __nv_bfloat16* __restrict__ vthi, const __nv_bfloat16* __restrict__ vtlo,
    __nv_bfloat16* __restrict__ ohi, __nv_bfloat16* __restrict__ olo)
{
    __shared__ __nv_bfloat16 sKh[64 * SK], sKl[64 * SK];
    __shared__ __nv_bfloat16 sVh[64 * SK], sVl[64 * SK];

    const int tid  = threadIdx.x;
    const int w    = tid >> 5;
    const int lane = tid & 31;
    const int tq   = lane >> 2;
    const int tr   = lane & 3;
    const int b    = blockIdx.x >> 4;
    const int h    = blockIdx.x & 15;
    const int q0   = blockIdx.y * 64;
    const float SCALE = 0.125f;

    // Q fragments, loaded once from gmem (32-bit loads of contiguous bf16 pairs)
    const long grow0 = (long)(b * LQ + q0 + w * 16 + tq);
    const __nv_bfloat16* qh0 = qhi + grow0 * DIM + h * HDIM;
    const __nv_bfloat16* ql0 = qlo + grow0 * DIM + h * HDIM;
    uint32_t aQh[4][4], aQl[4][4];
#pragma unroll
    for (int ks = 0; ks < 4; ks++) {
        const int c0 = ks * 16 + 2 * tr;
        aQh[ks][0] = *(const uint32_t*)&qh0[c0];
        aQh[ks][1] = *(const uint32_t*)&qh0[8 * DIM + c0];
        aQh[ks][2] = *(const uint32_t*)&qh0[c0 + 8];
        aQh[ks][3] = *(const uint32_t*)&qh0[8 * DIM + c0 + 8];
        aQl[ks][0] = *(const uint32_t*)&ql0[c0];
        aQl[ks][1] = *(const uint32_t*)&ql0[8 * DIM + c0];
        aQl[ks][2] = *(const uint32_t*)&ql0[c0 + 8];
        aQl[ks][3] = *(const uint32_t*)&ql0[8 * DIM + c0 + 8];
    }

    float oacc[8][4];
#pragma unroll
    for (int i = 0; i < 8; i++)
#pragma unroll
        for (int j = 0; j < 4; j++) oacc[i][j] = 0.f;
    float m[2] = {-1e30f, -1e30f}, l[2] = {0.f, 0.f};

    // loader mapping: row = tid>>1 (0..63), half = tid&1 (cols 0..31 / 32..63)
    const int lrow = tid >> 1, lhalf = (tid & 1) * 32;

    for (int j0 = 0; j0 < LKV; j0 += 64) {
        __syncthreads();
        {
            const __nv_bfloat16* kh_g = khi + ((long)(b * LKV + j0 + lrow)) * DIM + h * HDIM + lhalf;
            const __nv_bfloat16* kl_g = klo + ((long)(b * LKV + j0 + lrow)) * DIM + h * HDIM + lhalf;
            const long vb = ((long)((b * NHEADS + h) * HDIM + lrow)) * LKV + j0 + lhalf;
            const __nv_bfloat16* vh_g = vthi + vb;
            const __nv_bfloat16* vl_g = vtlo + vb;
#pragma unroll
            for (int u = 0; u < 4; u++) {
                const int so = lrow * SK + lhalf + u * 8;
                *(uint4*)&sKh[so] = *(const uint4*)&kh_g[u * 8];
                *(uint4*)&sKl[so] = *(const uint4*)&kl_g[u * 8];
                *(uint4*)&sVh[so] = *(const uint4*)&vh_g[u * 8];
                *(uint4*)&sVl[so] = *(const uint4*)&vl_g[u * 8];
            }
        }
        __syncthreads();

        // ---- S = Q K^T (bf16x3) ----
        float s[8][4];
#pragma unroll
        for (int i = 0; i < 8; i++)
#pragma unroll
            for (int j = 0; j < 4; j++) s[i][j] = 0.f;

#pragma unroll
        for (int ks = 0; ks < 4; ks++) {
            const int kb = ks * 16 + 2 * tr;
#pragma unroll
            for (int nf = 0; nf < 8; nf++) {
                const int rB = (nf * 8 + tq) * SK + kb;
                uint32_t bh[2], bl[2];
                bh[0] = *(const uint32_t*)&sKh[rB];
                bh[1] = *(const uint32_t*)&sKh[rB + 8];
                bl[0] = *(const uint32_t*)&sKl[rB];
                bl[1] = *(const uint32_t*)&sKl[rB + 8];
                MMA16816(s[nf], aQh[ks], bh);
                MMA16816(s[nf], aQh[ks], bl);
                MMA16816(s[nf], aQl[ks], bh);
            }
        }

        // ---- online softmax (rows tq and tq+8); scale folded into exp arg ----
#pragma unroll
        for (int r = 0; r < 2; r++) {
            float mx = -1e30f;
#pragma unroll
            for (int nf = 0; nf < 8; nf++)
                mx = fmaxf(mx, fmaxf(s[nf][2 * r], s[nf][2 * r + 1]));
            mx = fmaxf(mx, __shfl_xor_sync(0xffffffffu, mx, 1));
            mx = fmaxf(mx, __shfl_xor_sync(0xffffffffu, mx, 2));
            const float mn = fmaxf(m[r], mx);
            const float f  = __expf((m[r] - mn) * SCALE);
            float rs = 0.f;
#pragma unroll
            for (int nf = 0; nf < 8; nf++) {
                s[nf][2 * r]     = __expf((s[nf][2 * r]     - mn) * SCALE);
                s[nf][2 * r + 1] = __expf((s[nf][2 * r + 1] - mn) * SCALE);
                rs += s[nf][2 * r] + s[nf][2 * r + 1];
            }
            rs += __shfl_xor_sync(0xffffffffu, rs, 1);
            rs += __shfl_xor_sync(0xffffffffu, rs, 2);
            m[r] = mn;
            l[r] = l[r] * f + rs;
#pragma unroll
            for (int nf = 0; nf < 8; nf++) {
                oacc[nf][2 * r]     *= f;
                oacc[nf][2 * r + 1] *= f;
            }
        }

        // ---- O += P V (P hi/lo in registers; bf16x3) ----
#pragma unroll
        for (int ks = 0; ks < 4; ks++) {
            // A frags from s[2ks] (cols kb..kb+1 rows tq,tq+8) and s[2ks+1] (cols +8)
            float v0 = s[2 * ks][0],     v1 = s[2 * ks][1];
            float v2 = s[2 * ks][2],     v3 = s[2 * ks][3];
            float v4 = s[2 * ks + 1][0], v5 = s[2 * ks + 1][1];
            float v6 = s[2 * ks + 1][2], v7 = s[2 * ks + 1][3];
            __nv_bfloat16 h0 = __float2bfloat16(v0), h1 = __float2bfloat16(v1);
            __nv_bfloat16 h2 = __float2bfloat16(v2), h3 = __float2bfloat16(v3);
            __nv_bfloat16 h4 = __float2bfloat16(v4), h5 = __float2bfloat16(v5);
            __nv_bfloat16 h6 = __float2bfloat16(v6), h7 = __float2bfloat16(v7);
            uint32_t aPh[4], aPl[4];
            aPh[0] = packbf2(v0, v1); aPh[1] = packbf2(v2, v3);
            aPh[2] = packbf2(v4, v5); aPh[3] = packbf2(v6, v7);
            aPl[0] = packbf2(v0 - __bfloat162float(h0), v1 - __bfloat162float(h1));
            aPl[1] = packbf2(v2 - __bfloat162float(h2), v3 - __bfloat162float(h3));
            aPl[2] = packbf2(v4 - __bfloat162float(h4), v5 - __bfloat162float(h5));
            aPl[3] = packbf2(v6 - __bfloat162float(h6), v7 - __bfloat162float(h7));

            const int kb = ks * 16 + 2 * tr;
#pragma unroll
            for (int nf = 0; nf < 8; nf++) {
                const int rB = (nf * 8 + tq) * SK + kb;
                uint32_t bh[2], bl[2];
                bh[0] = *(const uint32_t*)&sVh[rB];
                bh[1] = *(const uint32_t*)&sVh[rB + 8];
                bl[0] = *(const uint32_t*)&sVl[rB];
                bl[1] = *(const uint32_t*)&sVl[rB + 8];
                MMA16816(oacc[nf], aPh, bh);
                MMA16816(oacc[nf], aPh, bl);
                MMA16816(oacc[nf], aPl, bh);
            }
        }
    }

    // ---- epilogue: O /= l, write bf16 hi/lo ----
    const float inv0 = 1.f / l[0], inv1 = 1.f / l[1];
    __nv_bfloat16* oh0 = ohi + grow0 * DIM + h * HDIM;
    __nv_bfloat16* ol0 = olo + grow0 * DIM + h * HDIM;
#pragma unroll
    for (int nf = 0; nf < 8; nf++) {
        const int col = nf * 8 + 2 * tr;
        float x0 = oacc[nf][0] * inv0, y0 = oacc[nf][1] * inv0;
        float x1 = oacc[nf][2] * inv1, y1 = oacc[nf][3] * inv1;
        __nv_bfloat16 hx0 = __float2bfloat16(x0), hy0 = __float2bfloat16(y0);
        __nv_bfloat16 hx1 = __float2bfloat16(x1), hy1 = __float2bfloat16(y1);
        *(uint32_t*)&oh0[col]           = packbf2(x0, y0);
        *(uint32_t*)&oh0[8 * DIM + col] = packbf2(x1, y1);
        *(uint32_t*)&ol0[col]           = packbf2(x0 - __bfloat162float(hx0), y0 - __bfloat162float(hy0));
        *(uint32_t*)&ol0[8 * DIM + col] = packbf2(x1 - __bfloat162float(hx1), y1 - __bfloat162float(hy1));
    }
}

// ----------------------------------------------------------------------------
// Launch
// ----------------------------------------------------------------------------
extern "C" void kernel_launch(void* const* d_in, const int* in_sizes, int n_in,
                              void* d_out, int out_size)
{
    const float* x     = (const float*)d_in[0];
    const float* y     = (const float*)d_in[1];
    const float* x_cos = (const float*)d_in[2];
    const float* x_sin = (const float*)d_in[3];
    const float* y_cos = (const float*)d_in[4];
    const float* y_sin = (const float*)d_in[5];
    const float* Wq    = (const float*)d_in[6];
    const float* bq    = (const float*)d_in[7];
    const float* Wk    = (const float*)d_in[8];
    const float* bk    = (const float*)d_in[9];
    const float* Wv    = (const float*)d_in[10];
    const float* bv    = (const float*)d_in[11];
    const float* Wo    = (const float*)d_in[12];
    const float* bo    = (const float*)d_in[13];
    const float* gq    = (const float*)d_in[14];
    const float* gk    = (const float*)d_in[15];
    float* out = (float*)d_out;

    float *qtmp, *ktmp, *vb;
    cudaGetSymbolAddress((void**)&qtmp, g_qtmp);
    cudaGetSymbolAddress((void**)&ktmp, g_ktmp);
    cudaGetSymbolAddress((void**)&vb,   g_v);

    __nv_bfloat16 *qhi, *qlo, *khi, *klo, *vthi, *vtlo;
    __nv_bfloat16 *xhi, *xlo, *yhi, *ylo;
    __nv_bfloat16 *wqh, *wql, *wkh, *wkl, *wvh, *wvl, *woh, *wol;
    cudaGetSymbolAddress((void**)&qhi, g_qhi);
    cudaGetSymbolAddress((void**)&qlo, g_qlo);
    cudaGetSymbolAddress((void**)&khi, g_khi);
    cudaGetSymbolAddress((void**)&klo, g_klo);
    cudaGetSymbolAddress((void**)&vthi, g_vthi);
    cudaGetSymbolAddress((void**)&vtlo, g_vtlo);
    cudaGetSymbolAddress((void**)&xhi, g_xhi);
    cudaGetSymbolAddress((void**)&xlo, g_xlo);
    cudaGetSymbolAddress((void**)&yhi, g_yhi);
    cudaGetSymbolAddress((void**)&ylo, g_ylo);
    cudaGetSymbolAddress((void**)&wqh, g_wqt_hi);
    cudaGetSymbolAddress((void**)&wql, g_wqt_lo);
    cudaGetSymbolAddress((void**)&wkh, g_wkt_hi);
    cudaGetSymbolAddress((void**)&wkl, g_wkt_lo);
    cudaGetSymbolAddress((void**)&wvh, g_wvt_hi);
    cudaGetSymbolAddress((void**)&wvl, g_wvt_lo);
    cudaGetSymbolAddress((void**)&woh, g_wot_hi);
    cudaGetSymbolAddress((void**)&wol, g_wot_lo);

    const int Mq = BATCH * LQ;    // 8192
    const int Mk = BATCH * LKV;   // 2048

    // Split activations + weights
    split_bf16_kernel<<<(Mq * DIM / 4 + 255) / 256, 256>>>(x, xhi, xlo, Mq * DIM / 4);
    split_bf16_kernel<<<(Mk * KV_DIM / 4 + 255) / 256, 256>>>(y, yhi, ylo, Mk * KV_DIM / 4);
    split_transpose_kernel<<<dim3(DIM / 32, DIM / 32),    256>>>(Wq, wqh, wql, DIM,    DIM);
    split_transpose_kernel<<<dim3(DIM / 32, KV_DIM / 32), 256>>>(Wk, wkh, wkl, KV_DIM, DIM);
    split_transpose_kernel<<<dim3(DIM / 32, KV_DIM / 32), 256>>>(Wv, wvh, wvl, KV_DIM, DIM);
    split_transpose_kernel<<<dim3(DIM / 32, DIM / 32),    256>>>(Wo, woh, wol, DIM,    DIM);

    // Projections (mma.sync bf16x3)
    gemm_bf16x3_mma_kernel<<<dim3(DIM / 128, Mq / 128), 256>>>(
        xhi, xlo, wqh, wql, bq, qtmp, Mq, DIM, DIM);
    gemm_bf16x3_mma_kernel<<<dim3(DIM / 128, Mk / 128), 256>>>(
        yhi, ylo, wkh, wkl, bk, ktmp, Mk, DIM, KV_DIM);
    gemm_bf16x3_mma_kernel<<<dim3(DIM / 128, Mk / 128), 256>>>(
        yhi, ylo, wvh, wvl, bv, vb, Mk, DIM, KV_DIM);

    // RMSNorm + RoPE -> bf16 hi/lo; V -> transposed bf16 hi/lo
    normrope_bf16_kernel<<<Mq, 256>>>(qtmp, qhi, qlo, gq, x_cos, x_sin);
    normrope_bf16_kernel<<<Mk, 256>>>(ktmp, khi, klo, gk, y_cos, y_sin);
    vtrans_split_kernel<<<dim3(DIM / 32, Mk / 32), 256>>>(vb, vthi, vtlo);

    // Flash attention (tensor cores) -> writes hi/lo bf16 into x-split buffers
    attn_mma_kernel<<<dim3(BATCH * NHEADS, LQ / 64), 128>>>(
        qhi, qlo, khi, klo, vthi, vtlo, xhi, xlo);

    // Output projection
    gemm_bf16x3_mma_kernel<<<dim3(DIM / 128, Mq / 128), 256>>>(
        xhi, xlo, woh, wol, bo, out, Mq, DIM, DIM);
}

// round 8
// speedup vs baseline: 2.5142x; 1.1059x over previous
#include <cuda_runtime.h>
#include <cuda_bf16.h>
#include <cstdint>

// ----------------------------------------------------------------------------
// Problem constants
// ----------------------------------------------------------------------------
#define BATCH   2
#define LQ      4096
#define LKV     1024
#define DIM     1024
#define KV_DIM  768
#define NHEADS  16
#define HDIM    64

// ----------------------------------------------------------------------------
// Scratch (device globals; allocation-free per harness rules)
// ----------------------------------------------------------------------------
__device__ float g_qtmp[(BATCH*LQ)*DIM];   // Q proj out (fp32)
__device__ float g_ktmp[(BATCH*LKV)*DIM];  // K proj out (fp32)
__device__ float g_v   [(BATCH*LKV)*DIM];  // V proj out (fp32)

__device__ __nv_bfloat16 g_qhi[(BATCH*LQ)*DIM],  g_qlo[(BATCH*LQ)*DIM];
__device__ __nv_bfloat16 g_khi[(BATCH*LKV)*DIM], g_klo[(BATCH*LKV)*DIM];
__device__ __nv_bfloat16 g_vthi[(BATCH*LKV)*DIM], g_vtlo[(BATCH*LKV)*DIM]; // V^T [b,h,d,c]

__device__ __nv_bfloat16 g_xhi[(BATCH*LQ)*DIM],  g_xlo[(BATCH*LQ)*DIM];   // x split; later attn-out split
__device__ __nv_bfloat16 g_yhi[(BATCH*LKV)*KV_DIM], g_ylo[(BATCH*LKV)*KV_DIM];
__device__ __nv_bfloat16 g_wqt_hi[DIM*DIM],    g_wqt_lo[DIM*DIM];
__device__ __nv_bfloat16 g_wkt_hi[DIM*KV_DIM], g_wkt_lo[DIM*KV_DIM];
__device__ __nv_bfloat16 g_wvt_hi[DIM*KV_DIM], g_wvt_lo[DIM*KV_DIM];
__device__ __nv_bfloat16 g_wot_hi[DIM*DIM],    g_wot_lo[DIM*DIM];

// ----------------------------------------------------------------------------
// mma.sync / cp.async helpers (baseline PTX, OK for compute_103 virtual target)
// ----------------------------------------------------------------------------
#define MMA16816(d, a, b) \
    asm volatile("mma.sync.aligned.m16n8k16.row.col.f32.bf16.bf16.f32 " \
        "{%0,%1,%2,%3}, {%4,%5,%6,%7}, {%8,%9}, {%0,%1,%2,%3};" \
        : "+f"((d)[0]), "+f"((d)[1]), "+f"((d)[2]), "+f"((d)[3]) \
        : "r"((a)[0]), "r"((a)[1]), "r"((a)[2]), "r"((a)[3]), \
          "r"((b)[0]), "r"((b)[1]))

#define CP16(sp, gp) do { \
    uint32_t _s = (uint32_t)__cvta_generic_to_shared(sp); \
    asm volatile("cp.async.cg.shared.global [%0], [%1], 16;" :: "r"(_s), "l"(gp)); \
} while (0)
#define CP_COMMIT()  asm volatile("cp.async.commit_group;" ::: "memory")
#define CP_WAIT1()   asm volatile("cp.async.wait_group 1;" ::: "memory")

__device__ __forceinline__ uint32_t packbf2(float x, float y) {
    __nv_bfloat162 t = __float22bfloat162_rn(make_float2(x, y));
    return *reinterpret_cast<uint32_t*>(&t);
}

// ----------------------------------------------------------------------------
// bf16x3 GEMM, 2-stage cp.async pipeline:
//   C[M,N] = A[M,K] @ Bt[N,K]^T + bias
//   CTA tile 128x128, BK=32, 256 threads (2x4 warps), warp tile 64x32.
//   acc += Ahi*Bhi + Ahi*Blo + Alo*Bhi (fp32).
// ----------------------------------------------------------------------------
#define SSTR 40
#define GEMM_STAGE_ELEMS (4 * 128 * SSTR)                 // Ahi,Alo,Bhi,Blo
#define GEMM_SMEM_BYTES  (2 * GEMM_STAGE_ELEMS * 2)       // 81920 B

__global__ __launch_bounds__(256, 2) void gemm_bf16x3_mma_kernel(
    const __nv_bfloat16* __restrict__ Ahi, const __nv_bfloat16* __restrict__ Alo,
    const __nv_bfloat16* __restrict__ Bhi, const __nv_bfloat16* __restrict__ Blo,
    const float* __restrict__ bias, float* __restrict__ C,
    int M, int N, int K)
{
    extern __shared__ __nv_bfloat16 dsm[];

    const int tid  = threadIdx.x;
    const int wid  = tid >> 5;
    const int lane = tid & 31;
    const int warpM = wid >> 2;
    const int warpN = wid & 3;
    const int bm = blockIdx.y * 128;
    const int bn = blockIdx.x * 128;
    const int tq = lane >> 2;
    const int tr = lane & 3;

    // loader mapping: thread covers rows r0g and r0g+64, 8 bf16 cols at c0g
    const int r0g = tid >> 2;
    const int r1g = r0g + 64;
    const int c0g = (tid & 3) * 8;

    float acc[4][4][4];
#pragma unroll
    for (int i = 0; i < 4; i++)
#pragma unroll
        for (int j = 0; j < 4; j++)
#pragma unroll
            for (int r = 0; r < 4; r++) acc[i][j][r] = 0.f;

    const int nchunks = K >> 5;

    // issue chunk c into stage s
    auto issue = [&](int c, int s) {
        __nv_bfloat16* sAh = dsm + s * GEMM_STAGE_ELEMS;
        __nv_bfloat16* sAl = sAh + 128 * SSTR;
        __nv_bfloat16* sBh = sAl + 128 * SSTR;
        __nv_bfloat16* sBl = sBh + 128 * SSTR;
        const int k0 = c << 5;
        const long a0 = (long)(bm + r0g) * K + k0 + c0g;
        const long a1 = (long)(bm + r1g) * K + k0 + c0g;
        const long b0 = (long)(bn + r0g) * K + k0 + c0g;
        const long b1 = (long)(bn + r1g) * K + k0 + c0g;
        CP16(&sAh[r0g * SSTR + c0g], &Ahi[a0]);
        CP16(&sAh[r1g * SSTR + c0g], &Ahi[a1]);
        CP16(&sAl[r0g * SSTR + c0g], &Alo[a0]);
        CP16(&sAl[r1g * SSTR + c0g], &Alo[a1]);
        CP16(&sBh[r0g * SSTR + c0g], &Bhi[b0]);
        CP16(&sBh[r1g * SSTR + c0g], &Bhi[b1]);
        CP16(&sBl[r0g * SSTR + c0g], &Blo[b0]);
        CP16(&sBl[r1g * SSTR + c0g], &Blo[b1]);
    };

    issue(0, 0);
    CP_COMMIT();

    for (int c = 0; c < nchunks; c++) {
        if (c + 1 < nchunks) issue(c + 1, (c + 1) & 1);
        CP_COMMIT();
        CP_WAIT1();
        __syncthreads();

        const __nv_bfloat16* sAh = dsm + (c & 1) * GEMM_STAGE_ELEMS;
        const __nv_bfloat16* sAl = sAh + 128 * SSTR;
        const __nv_bfloat16* sBh = sAl + 128 * SSTR;
        const __nv_bfloat16* sBl = sBh + 128 * SSTR;

#pragma unroll
        for (int ks = 0; ks < 2; ks++) {
            const int kb = ks * 16 + tr * 2;
            uint32_t ah[4][4], al[4][4];
#pragma unroll
            for (int mf = 0; mf < 4; mf++) {
                const int rA = warpM * 64 + mf * 16 + tq;
                ah[mf][0] = *(const uint32_t*)&sAh[(rA    ) * SSTR + kb    ];
                ah[mf][1] = *(const uint32_t*)&sAh[(rA + 8) * SSTR + kb    ];
                ah[mf][2] = *(const uint32_t*)&sAh[(rA    ) * SSTR + kb + 8];
                ah[mf][3] = *(const uint32_t*)&sAh[(rA + 8) * SSTR + kb + 8];
                al[mf][0] = *(const uint32_t*)&sAl[(rA    ) * SSTR + kb    ];
                al[mf][1] = *(const uint32_t*)&sAl[(rA + 8) * SSTR + kb    ];
                al[mf][2] = *(const uint32_t*)&sAl[(rA    ) * SSTR + kb + 8];
                al[mf][3] = *(const uint32_t*)&sAl[(rA + 8) * SSTR + kb + 8];
            }
#pragma unroll
            for (int nf = 0; nf < 4; nf++) {
                const int rB = warpN * 32 + nf * 8 + tq;
                uint32_t bh[2], bl[2];
                bh[0] = *(const uint32_t*)&sBh[rB * SSTR + kb    ];
                bh[1] = *(const uint32_t*)&sBh[rB * SSTR + kb + 8];
                bl[0] = *(const uint32_t*)&sBl[rB * SSTR + kb    ];
                bl[1] = *(const uint32_t*)&sBl[rB * SSTR + kb + 8];
#pragma unroll
                for (int mf = 0; mf < 4; mf++) {
                    MMA16816(acc[mf][nf], ah[mf], bh);
                    MMA16816(acc[mf][nf], ah[mf], bl);
                    MMA16816(acc[mf][nf], al[mf], bh);
                }
            }
        }
        __syncthreads();
    }

#pragma unroll
    for (int mf = 0; mf < 4; mf++) {
        const int row = bm + warpM * 64 + mf * 16 + tq;
#pragma unroll
        for (int nf = 0; nf < 4; nf++) {
            const int col = bn + warpN * 32 + nf * 8 + tr * 2;
            const float b0 = bias[col], b1 = bias[col + 1];
            float2 v0 = make_float2(acc[mf][nf][0] + b0, acc[mf][nf][1] + b1);
            float2 v1 = make_float2(acc[mf][nf][2] + b0, acc[mf][nf][3] + b1);
            *(float2*)&C[(long)row * N + col]       = v0;
            *(float2*)&C[(long)(row + 8) * N + col] = v1;
        }
    }
}

// ----------------------------------------------------------------------------
// Split fp32 -> bf16 hi + lo (elementwise)
// ----------------------------------------------------------------------------
__global__ __launch_bounds__(256) void split_bf16_kernel(
    const float* __restrict__ src, __nv_bfloat16* __restrict__ hi,
    __nv_bfloat16* __restrict__ lo, int n4)
{
    int i = blockIdx.x * blockDim.x + threadIdx.x;
    if (i >= n4) return;
    float4 v = *(const float4*)&src[(long)i * 4];
    __nv_bfloat16 h0 = __float2bfloat16(v.x), h1 = __float2bfloat16(v.y);
    __nv_bfloat16 h2 = __float2bfloat16(v.z), h3 = __float2bfloat16(v.w);
    uint32_t ph0 = packbf2(v.x, v.y), ph1 = packbf2(v.z, v.w);
    uint32_t pl0 = packbf2(v.x - __bfloat162float(h0), v.y - __bfloat162float(h1));
    uint32_t pl1 = packbf2(v.z - __bfloat162float(h2), v.w - __bfloat162float(h3));
    *(uint2*)&hi[(long)i * 4] = make_uint2(ph0, ph1);
    *(uint2*)&lo[(long)i * 4] = make_uint2(pl0, pl1);
}

// ----------------------------------------------------------------------------
// Split + transpose: W [K,N] fp32 -> Wt hi/lo [N,K] bf16
// ----------------------------------------------------------------------------
__global__ __launch_bounds__(256) void split_transpose_kernel(
    const float* __restrict__ W, __nv_bfloat16* __restrict__ Thi,
    __nv_bfloat16* __restrict__ Tlo, int K, int N)
{
    __shared__ float tile[32][33];
    const int bx = blockIdx.x * 32;
    const int by = blockIdx.y * 32;
    const int tx = threadIdx.x & 31;
    const int ty = threadIdx.x >> 5;
#pragma unroll
    for (int i = 0; i < 4; i++) {
        int kk = by + ty + i * 8;
        tile[ty + i * 8][tx] = W[(long)kk * N + bx + tx];
    }
    __syncthreads();
#pragma unroll
    for (int i = 0; i < 4; i++) {
        int nn = bx + ty + i * 8;
        float v = tile[tx][ty + i * 8];
        __nv_bfloat16 h = __float2bfloat16(v);
        __nv_bfloat16 l = __float2bfloat16(v - __bfloat162float(h));
        Thi[(long)nn * K + by + tx] = h;
        Tlo[(long)nn * K + by + tx] = l;
    }
}

// ----------------------------------------------------------------------------
// V transpose-split: V [B*Lkv, DIM] fp32 -> Vt hi/lo [b,h,d][Lkv] bf16
// ----------------------------------------------------------------------------
__global__ __launch_bounds__(256) void vtrans_split_kernel(
    const float* __restrict__ V, __nv_bfloat16* __restrict__ Thi,
    __nv_bfloat16* __restrict__ Tlo)
{
    __shared__ float tile[32][33];
    const int bx = blockIdx.x * 32;   // col base (h*64+d)
    const int by = blockIdx.y * 32;   // row base (b*1024+c)
    const int tx = threadIdx.x & 31;
    const int ty = threadIdx.x >> 5;
#pragma unroll
    for (int i = 0; i < 4; i++) {
        int rr = by + ty + i * 8;
        tile[ty + i * 8][tx] = V[(long)rr * DIM + bx + tx];
    }
    __syncthreads();
#pragma unroll
    for (int i = 0; i < 4; i++) {
        int colg = bx + ty + i * 8;
        int rowg = by + tx;
        int b = rowg >> 10, c = rowg & 1023;
        int h = colg >> 6,  d = colg & 63;
        float v = tile[tx][ty + i * 8];
        __nv_bfloat16 hh = __float2bfloat16(v);
        __nv_bfloat16 ll = __float2bfloat16(v - __bfloat162float(hh));
        long o = ((long)((b * NHEADS + h) * HDIM + d)) * LKV + c;
        Thi[o] = hh;
        Tlo[o] = ll;
    }
}

// ----------------------------------------------------------------------------
// Fused RMSNorm + RoPE -> bf16 hi/lo outputs
// ----------------------------------------------------------------------------
__global__ __launch_bounds__(256) void normrope_bf16_kernel(
    const float* __restrict__ in, __nv_bfloat16* __restrict__ outhi,
    __nv_bfloat16* __restrict__ outlo,
    const float* __restrict__ g, const float* __restrict__ cosb,
    const float* __restrict__ sinb)
{
    const int row = blockIdx.x;
    const float* h = in + (long)row * DIM;
    const int tid = threadIdx.x;
    const int e = tid << 2;

    float4 t = *(const float4*)&h[e];
    float ss = t.x * t.x + t.y * t.y + t.z * t.z + t.w * t.w;
#pragma unroll
    for (int o = 16; o > 0; o >>= 1)
        ss += __shfl_xor_sync(0xffffffffu, ss, o);
    __shared__ float red[8];
    if ((tid & 31) == 0) red[tid >> 5] = ss;
    __syncthreads();
    float tot = red[0] + red[1] + red[2] + red[3] + red[4] + red[5] + red[6] + red[7];
    float inv = rsqrtf(tot * (1.0f / (float)DIM) + 1e-6f);

    const int d   = e & (HDIM - 1);
    const int po  = (d < 32) ? 32 : -32;
    const float sgn = (d < 32) ? -1.0f : 1.0f;

    float4 tp  = *(const float4*)&h[e + po];
    float4 g4  = *(const float4*)&g[e];
    float4 gp4 = *(const float4*)&g[e + po];
    float4 c4  = *(const float4*)&cosb[(long)row * HDIM + d];
    float4 s4  = *(const float4*)&sinb[(long)row * HDIM + d];

    float4 o4;
    o4.x = t.x * inv * g4.x * c4.x + sgn * tp.x * inv * gp4.x * s4.x;
    o4.y = t.y * inv * g4.y * c4.y + sgn * tp.y * inv * gp4.y * s4.y;
    o4.z = t.z * inv * g4.z * c4.z + sgn * tp.z * inv * gp4.z * s4.z;
    o4.w = t.w * inv * g4.w * c4.w + sgn * tp.w * inv * gp4.w * s4.w;

    __nv_bfloat16 h0 = __float2bfloat16(o4.x), h1 = __float2bfloat16(o4.y);
    __nv_bfloat16 h2 = __float2bfloat16(o4.z), h3 = __float2bfloat16(o4.w);
    uint32_t ph0 = packbf2(o4.x, o4.y), ph1 = packbf2(o4.z, o4.w);
    uint32_t pl0 = packbf2(o4.x - __bfloat162float(h0), o4.y - __bfloat162float(h1));
    uint32_t pl1 = packbf2(o4.z - __bfloat162float(h2), o4.w - __bfloat162float(h3));
    *(uint2*)&outhi[(long)row * DIM + e] = make_uint2(ph0, ph1);
    *(uint2*)&outlo[(long)row * DIM + e] = make_uint2(pl0, pl1);
}

// ----------------------------------------------------------------------------
// Flash attention, bf16x3 mma.sync, 2-stage cp.async pipeline.
// CTA = 128 threads (4 warps), 64 q-rows per CTA. KV chunks of 64.
// ----------------------------------------------------------------------------
#define SK 72
#define ATT_STAGE_ELEMS (4 * 64 * SK)                 // Kh,Kl,Vh,Vl
#define ATT_SMEM_BYTES  (2 * ATT_STAGE_ELEMS * 2)     // 73728 B

__global__ __launch_bounds__(128, 3) void attn_mma_kernel(
    const __nv_bfloat16* __restrict__ qhi, const __nv_bfloat16* __restrict__ qlo,
    const __nv_bfloat16* __restrict__ khi, const __nv_bfloat16* __restrict__ klo,
    const __nv_bfloat16* __restrict__ vthi, const __nv_bfloat16* __restrict__ vtlo,
    __nv_bfloat16* __restrict__ ohi, __nv_bfloat16* __restrict__ olo)
{
    extern __shared__ __nv_bfloat16 dsm[];

    const int tid  = threadIdx.x;
    const int w    = tid >> 5;
    const int lane = tid & 31;
    const int tq   = lane >> 2;
    const int tr   = lane & 3;
    const int b    = blockIdx.x >> 4;
    const int h    = blockIdx.x & 15;
    const int q0   = blockIdx.y * 64;
    const float SCALE = 0.125f;

    // loader mapping: row = tid>>1 (0..63), half = tid&1 (cols 0..31 / 32..63)
    const int lrow = tid >> 1, lhalf = (tid & 1) * 32;

    auto issue = [&](int c, int s) {
        __nv_bfloat16* sKh = dsm + s * ATT_STAGE_ELEMS;
        __nv_bfloat16* sKl = sKh + 64 * SK;
        __nv_bfloat16* sVh = sKl + 64 * SK;
        __nv_bfloat16* sVl = sVh + 64 * SK;
        const int j0 = c << 6;
        const __nv_bfloat16* kh_g = khi + ((long)(b * LKV + j0 + lrow)) * DIM + h * HDIM + lhalf;
        const __nv_bfloat16* kl_g = klo + ((long)(b * LKV + j0 + lrow)) * DIM + h * HDIM + lhalf;
        const long vo = ((long)((b * NHEADS + h) * HDIM + lrow)) * LKV + j0 + lhalf;
        const __nv_bfloat16* vh_g = vthi + vo;
        const __nv_bfloat16* vl_g = vtlo + vo;
#pragma unroll
        for (int u = 0; u < 4; u++) {
            const int so = lrow * SK + lhalf + u * 8;
            CP16(&sKh[so], &kh_g[u * 8]);
            CP16(&sKl[so], &kl_g[u * 8]);
            CP16(&sVh[so], &vh_g[u * 8]);
            CP16(&sVl[so], &vl_g[u * 8]);
        }
    };

    // Q fragments, loaded once from gmem
    const long grow0 = (long)(b * LQ + q0 + w * 16 + tq);
    const __nv_bfloat16* qh0 = qhi + grow0 * DIM + h * HDIM;
    const __nv_bfloat16* ql0 = qlo + grow0 * DIM + h * HDIM;
    uint32_t aQh[4][4], aQl[4][4];
#pragma unroll
    for (int ks = 0; ks < 4; ks++) {
        const int c0 = ks * 16 + 2 * tr;
        aQh[ks][0] = *(const uint32_t*)&qh0[c0];
        aQh[ks][1] = *(const uint32_t*)&qh0[8 * DIM + c0];
        aQh[ks][2] = *(const uint32_t*)&qh0[c0 + 8];
        aQh[ks][3] = *(const uint32_t*)&qh0[8 * DIM + c0 + 8];
        aQl[ks][0] = *(const uint32_t*)&ql0[c0];
        aQl[ks][1] = *(const uint32_t*)&ql0[8 * DIM + c0];
        aQl[ks][2] = *(const uint32_t*)&ql0[c0 + 8];
        aQl[ks][3] = *(const uint32_t*)&ql0[8 * DIM + c0 + 8];
    }

    float oacc[8][4];
#pragma unroll
    for (int i = 0; i < 8; i++)
#pragma unroll
        for (int j = 0; j < 4; j++) oacc[i][j] = 0.f;
    float m[2] = {-1e30f, -1e30f}, l[2] = {0.f, 0.f};

    issue(0, 0);
    CP_COMMIT();

    const int NCH = LKV / 64;
    for (int c = 0; c < NCH; c++) {
        if (c + 1 < NCH) issue(c + 1, (c + 1) & 1);
        CP_COMMIT();
        CP_WAIT1();
        __syncthreads();

        const __nv_bfloat16* sKh = dsm + (c & 1) * ATT_STAGE_ELEMS;
        const __nv_bfloat16* sKl = sKh + 64 * SK;
        const __nv_bfloat16* sVh = sKl + 64 * SK;
        const __nv_bfloat16* sVl = sVh + 64 * SK;

        // ---- S = Q K^T (bf16x3) ----
        float s[8][4];
#pragma unroll
        for (int i = 0; i < 8; i++)
#pragma unroll
            for (int j = 0; j < 4; j++) s[i][j] = 0.f;

#pragma unroll
        for (int ks = 0; ks < 4; ks++) {
            const int kb = ks * 16 + 2 * tr;
#pragma unroll
            for (int nf = 0; nf < 8; nf++) {
                const int rB = (nf * 8 + tq) * SK + kb;
                uint32_t bh[2], bl[2];
                bh[0] = *(const uint32_t*)&sKh[rB];
                bh[1] = *(const uint32_t*)&sKh[rB + 8];
                bl[0] = *(const uint32_t*)&sKl[rB];
                bl[1] = *(const uint32_t*)&sKl[rB + 8];
                MMA16816(s[nf], aQh[ks], bh);
                MMA16816(s[nf], aQh[ks], bl);
                MMA16816(s[nf], aQl[ks], bh);
            }
        }

        // ---- online softmax (rows tq and tq+8) ----
#pragma unroll
        for (int r = 0; r < 2; r++) {
            float mx = -1e30f;
#pragma unroll
            for (int nf = 0; nf < 8; nf++)
                mx = fmaxf(mx, fmaxf(s[nf][2 * r], s[nf][2 * r + 1]));
            mx = fmaxf(mx, __shfl_xor_sync(0xffffffffu, mx, 1));
            mx = fmaxf(mx, __shfl_xor_sync(0xffffffffu, mx, 2));
            const float mn = fmaxf(m[r], mx);
            const float f  = __expf((m[r] - mn) * SCALE);
            float rs = 0.f;
#pragma unroll
            for (int nf = 0; nf < 8; nf++) {
                s[nf][2 * r]     = __expf((s[nf][2 * r]     - mn) * SCALE);
                s[nf][2 * r + 1] = __expf((s[nf][2 * r + 1] - mn) * SCALE);
                rs += s[nf][2 * r] + s[nf][2 * r + 1];
            }
            rs += __shfl_xor_sync(0xffffffffu, rs, 1);
            rs += __shfl_xor_sync(0xffffffffu, rs, 2);
            m[r] = mn;
            l[r] = l[r] * f + rs;
#pragma unroll
            for (int nf = 0; nf < 8; nf++) {
                oacc[nf][2 * r]     *= f;
                oacc[nf][2 * r + 1] *= f;
            }
        }

        // ---- O += P V (P hi/lo in registers; bf16x3) ----
#pragma unroll
        for (int ks = 0; ks < 4; ks++) {
            float v0 = s[2 * ks][0],     v1 = s[2 * ks][1];
            float v2 = s[2 * ks][2],     v3 = s[2 * ks][3];
            float v4 = s[2 * ks + 1][0], v5 = s[2 * ks + 1][1];
            float v6 = s[2 * ks + 1][2], v7 = s[2 * ks + 1][3];
            __nv_bfloat16 h0 = __float2bfloat16(v0), h1 = __float2bfloat16(v1);
            __nv_bfloat16 h2 = __float2bfloat16(v2), h3 = __float2bfloat16(v3);
            __nv_bfloat16 h4 = __float2bfloat16(v4), h5 = __float2bfloat16(v5);
            __nv_bfloat16 h6 = __float2bfloat16(v6), h7 = __float2bfloat16(v7);
            uint32_t aPh[4], aPl[4];
            aPh[0] = packbf2(v0, v1); aPh[1] = packbf2(v2, v3);
            aPh[2] = packbf2(v4, v5); aPh[3] = packbf2(v6, v7);
            aPl[0] = packbf2(v0 - __bfloat162float(h0), v1 - __bfloat162float(h1));
            aPl[1] = packbf2(v2 - __bfloat162float(h2), v3 - __bfloat162float(h3));
            aPl[2] = packbf2(v4 - __bfloat162float(h4), v5 - __bfloat162float(h5));
            aPl[3] = packbf2(v6 - __bfloat162float(h6), v7 - __bfloat162float(h7));

            const int kb = ks * 16 + 2 * tr;
#pragma unroll
            for (int nf = 0; nf < 8; nf++) {
                const int rB = (nf * 8 + tq) * SK + kb;
                uint32_t bh[2], bl[2];
                bh[0] = *(const uint32_t*)&sVh[rB];
                bh[1] = *(const uint32_t*)&sVh[rB + 8];
                bl[0] = *(const uint32_t*)&sVl[rB];
                bl[1] = *(const uint32_t*)&sVl[rB + 8];
                MMA16816(oacc[nf], aPh, bh);
                MMA16816(oacc[nf], aPh, bl);
                MMA16816(oacc[nf], aPl, bh);
            }
        }
        __syncthreads();
    }

    // ---- epilogue: O /= l, write bf16 hi/lo ----
    const float inv0 = 1.f / l[0], inv1 = 1.f / l[1];
    __nv_bfloat16* oh0 = ohi + grow0 * DIM + h * HDIM;
    __nv_bfloat16* ol0 = olo + grow0 * DIM + h * HDIM;
#pragma unroll
    for (int nf = 0; nf < 8; nf++) {
        const int col = nf * 8 + 2 * tr;
        float x0 = oacc[nf][0] * inv0, y0 = oacc[nf][1] * inv0;
        float x1 = oacc[nf][2] * inv1, y1 = oacc[nf][3] * inv1;
        __nv_bfloat16 hx0 = __float2bfloat16(x0), hy0 = __float2bfloat16(y0);
        __nv_bfloat16 hx1 = __float2bfloat16(x1), hy1 = __float2bfloat16(y1);
        *(uint32_t*)&oh0[col]           = packbf2(x0, y0);
        *(uint32_t*)&oh0[8 * DIM + col] = packbf2(x1, y1);
        *(uint32_t*)&ol0[col]           = packbf2(x0 - __bfloat162float(hx0), y0 - __bfloat162float(hy0));
        *(uint32_t*)&ol0[8 * DIM + col] = packbf2(x1 - __bfloat162float(hx1), y1 - __bfloat162float(hy1));
    }
}

// ----------------------------------------------------------------------------
// Launch
// ----------------------------------------------------------------------------
extern "C" void kernel_launch(void* const* d_in, const int* in_sizes, int n_in,
                              void* d_out, int out_size)
{
    const float* x     = (const float*)d_in[0];
    const float* y     = (const float*)d_in[1];
    const float* x_cos = (const float*)d_in[2];
    const float* x_sin = (const float*)d_in[3];
    const float* y_cos = (const float*)d_in[4];
    const float* y_sin = (const float*)d_in[5];
    const float* Wq    = (const float*)d_in[6];
    const float* bq    = (const float*)d_in[7];
    const float* Wk    = (const float*)d_in[8];
    const float* bk    = (const float*)d_in[9];
    const float* Wv    = (const float*)d_in[10];
    const float* bv    = (const float*)d_in[11];
    const float* Wo    = (const float*)d_in[12];
    const float* bo    = (const float*)d_in[13];
    const float* gq    = (const float*)d_in[14];
    const float* gk    = (const float*)d_in[15];
    float* out = (float*)d_out;

    float *qtmp, *ktmp, *vb;
    cudaGetSymbolAddress((void**)&qtmp, g_qtmp);
    cudaGetSymbolAddress((void**)&ktmp, g_ktmp);
    cudaGetSymbolAddress((void**)&vb,   g_v);

    __nv_bfloat16 *qhi, *qlo, *khi, *klo, *vthi, *vtlo;
    __nv_bfloat16 *xhi, *xlo, *yhi, *ylo;
    __nv_bfloat16 *wqh, *wql, *wkh, *wkl, *wvh, *wvl, *woh, *wol;
    cudaGetSymbolAddress((void**)&qhi, g_qhi);
    cudaGetSymbolAddress((void**)&qlo, g_qlo);
    cudaGetSymbolAddress((void**)&khi, g_khi);
    cudaGetSymbolAddress((void**)&klo, g_klo);
    cudaGetSymbolAddress((void**)&vthi, g_vthi);
    cudaGetSymbolAddress((void**)&vtlo, g_vtlo);
    cudaGetSymbolAddress((void**)&xhi, g_xhi);
    cudaGetSymbolAddress((void**)&xlo, g_xlo);
    cudaGetSymbolAddress((void**)&yhi, g_yhi);
    cudaGetSymbolAddress((void**)&ylo, g_ylo);
    cudaGetSymbolAddress((void**)&wqh, g_wqt_hi);
    cudaGetSymbolAddress((void**)&wql, g_wqt_lo);
    cudaGetSymbolAddress((void**)&wkh, g_wkt_hi);
    cudaGetSymbolAddress((void**)&wkl, g_wkt_lo);
    cudaGetSymbolAddress((void**)&wvh, g_wvt_hi);
    cudaGetSymbolAddress((void**)&wvl, g_wvt_lo);
    cudaGetSymbolAddress((void**)&woh, g_wot_hi);
    cudaGetSymbolAddress((void**)&wol, g_wot_lo);

    // Opt-in to >48KB dynamic smem (host-side, graph-capture neutral)
    cudaFuncSetAttribute(gemm_bf16x3_mma_kernel,
                         cudaFuncAttributeMaxDynamicSharedMemorySize, GEMM_SMEM_BYTES);
    cudaFuncSetAttribute(attn_mma_kernel,
                         cudaFuncAttributeMaxDynamicSharedMemorySize, ATT_SMEM_BYTES);

    const int Mq = BATCH * LQ;    // 8192
    const int Mk = BATCH * LKV;   // 2048

    // Split activations + weights
    split_bf16_kernel<<<(Mq * DIM / 4 + 255) / 256, 256>>>(x, xhi, xlo, Mq * DIM / 4);
    split_bf16_kernel<<<(Mk * KV_DIM / 4 + 255) / 256, 256>>>(y, yhi, ylo, Mk * KV_DIM / 4);
    split_transpose_kernel<<<dim3(DIM / 32, DIM / 32),    256>>>(Wq, wqh, wql, DIM,    DIM);
    split_transpose_kernel<<<dim3(DIM / 32, KV_DIM / 32), 256>>>(Wk, wkh, wkl, KV_DIM, DIM);
    split_transpose_kernel<<<dim3(DIM / 32, KV_DIM / 32), 256>>>(Wv, wvh, wvl, KV_DIM, DIM);
    split_transpose_kernel<<<dim3(DIM / 32, DIM / 32),    256>>>(Wo, woh, wol, DIM,    DIM);

    // Projections (mma.sync bf16x3, cp.async pipelined)
    gemm_bf16x3_mma_kernel<<<dim3(DIM / 128, Mq / 128), 256, GEMM_SMEM_BYTES>>>(
        xhi, xlo, wqh, wql, bq, qtmp, Mq, DIM, DIM);
    gemm_bf16x3_mma_kernel<<<dim3(DIM / 128, Mk / 128), 256, GEMM_SMEM_BYTES>>>(
        yhi, ylo, wkh, wkl, bk, ktmp, Mk, DIM, KV_DIM);
    gemm_bf16x3_mma_kernel<<<dim3(DIM / 128, Mk / 128), 256, GEMM_SMEM_BYTES>>>(
        yhi, ylo, wvh, wvl, bv, vb, Mk, DIM, KV_DIM);

    // RMSNorm + RoPE -> bf16 hi/lo; V -> transposed bf16 hi/lo
    normrope_bf16_kernel<<<Mq, 256>>>(qtmp, qhi, qlo, gq, x_cos, x_sin);
    normrope_bf16_kernel<<<Mk, 256>>>(ktmp, khi, klo, gk, y_cos, y_sin);
    vtrans_split_kernel<<<dim3(DIM / 32, Mk / 32), 256>>>(vb, vthi, vtlo);

    // Flash attention (tensor cores, cp.async pipelined)
    attn_mma_kernel<<<dim3(BATCH * NHEADS, LQ / 64), 128, ATT_SMEM_BYTES>>>(
        qhi, qlo, khi, klo, vthi, vtlo, xhi, xlo);

    // Output projection
    gemm_bf16x3_mma_kernel<<<dim3(DIM / 128, Mq / 128), 256, GEMM_SMEM_BYTES>>>(
        xhi, xlo, woh, wol, bo, out, Mq, DIM, DIM);
}